// round 5
// baseline (speedup 1.0000x reference)
#include <cuda_runtime.h>
#include <math.h>

#define NB   4
#define CPc  256
#define PLc  64
#define NQc  2304

static const int CRs[5] = {64, 256, 512, 1024, 2048};
static const int Ms [5] = {2304, 2304, 576, 144, 36};

typedef unsigned long long ull;

// ---------------------------------------------------------------------------
// Scratch
// ---------------------------------------------------------------------------
__device__ float    g_T  [NB * PLc * NQc];
__device__ float    g_PGw[2 * PLc * 2048];
__device__ float    g_PG [NB * 2 * PLc * NQc];
__device__ float    g_Lt [NB * NQc * NQc];
__device__ float    g_O  [NB * NQc * PLc];
__device__ float    g_Z  [NB * CPc * NQc];
__device__ unsigned g_mstU[NB * NQc];
__device__ float    g_sum [NB * NQc];
__device__ float    g_sinv[NB * NQc];
__device__ float    g_stat[2 * CPc];
__device__ float    g_mean[CPc];
__device__ float    g_istd[CPc];

// ---------------------------------------------------------------------------
// Helpers
// ---------------------------------------------------------------------------
__device__ __forceinline__ float fexp(float x)
{
    const float L2E = 1.4426950408889634f;
    float t = fmaf(x, L2E, 12582912.0f);
    float n = t - 12582912.0f;
    float f = fmaf(x, L2E, -n);
    float p = 1.33335581e-3f;
    p = fmaf(p, f, 9.61812911e-3f);
    p = fmaf(p, f, 5.55041087e-2f);
    p = fmaf(p, f, 2.40226507e-1f);
    p = fmaf(p, f, 6.93147180e-1f);
    p = fmaf(p, f, 1.0f);
    int ni = (int)n;
    ni = max(-126, min(127, ni));
    return p * __int_as_float((ni + 127) << 23);
}

__device__ __forceinline__ unsigned fenc(float x)
{
    unsigned b = __float_as_uint(x);
    return (b & 0x80000000u) ? ~b : (b | 0x80000000u);
}
__device__ __forceinline__ float fdec(unsigned k)
{
    return __uint_as_float((k & 0x80000000u) ? (k & 0x7FFFFFFFu) : ~k);
}

// packed fp32x2 FMA (Blackwell FFMA2) and lane-duplicate pack
__device__ __forceinline__ void ffma2(ull& c, ull a, ull b)
{
    asm("fma.rn.f32x2 %0, %1, %2, %0;" : "+l"(c) : "l"(a), "l"(b));
}
__device__ __forceinline__ ull dup2(float x)
{
    ull r;
    unsigned u = __float_as_uint(x);
    asm("mov.b64 %0, {%1, %1};" : "=l"(r) : "r"(u));
    return r;
}

// ---------------------------------------------------------------------------
// Tiled SGEMM, double-buffered smem, reg prefetch, FFMA2 microkernel
// (accumulators paired along M), fused softmax / BN extras.
// ---------------------------------------------------------------------------
template<int BM, int BN, int TM, int TN, bool TAR, bool TBR,
         bool EXPA, bool CMAX, bool DIVB, bool STAT, bool ATOM>
__global__ void __launch_bounds__(256) gemm_k(
    const float* __restrict__ A, const float* __restrict__ B, float* __restrict__ C,
    int M, int N, int K, int lda, int ldb, int ldc,
    long sA, long sB, long sC, int ksplit, int kchunk,
    const unsigned* __restrict__ mstIn, unsigned* __restrict__ mstOut,
    float* __restrict__ sumOut, const float* __restrict__ sinv,
    float* __restrict__ statOut, int sStat)
{
    constexpr int BK = 16;
    constexpr int LA = BM * BK / 1024;
    constexpr int LB = BN * BK / 1024;
    constexpr int MV = BM / 4, NV = BN / 4;
    constexpr int TX = BN / TN;
    static_assert((BM / TM) * (BN / TN) == 256, "256 threads");
    static_assert(TM % 2 == 0, "TM even");

    __shared__ float As[2][BK][BM];
    __shared__ float Bs[2][BK][BN + (TBR ? 1 : 0)];

    const int b  = blockIdx.z / ksplit;
    const int kz = blockIdx.z - b * ksplit;
    A += (long)b * sA;  B += (long)b * sB;  C += (long)b * sC;

    const int kbeg = kz * kchunk;
    const int kend = min(K, kbeg + kchunk);
    const int m0 = blockIdx.y * BM, n0 = blockIdx.x * BN;
    const int tid = threadIdx.x;
    const int ty = tid / TX, tx = tid - ty * TX;

    float4 ra[LA], rb[LB];
    float mxv[LA][4];
    float sacc[LA][4];

    if (EXPA) {
#pragma unroll
        for (int r = 0; r < LA; r++) {
            int e = tid + r * 256;
            int mq = e - (e / MV) * MV;
            int gm = m0 + mq * 4;
#pragma unroll
            for (int q = 0; q < 4; q++) {
                mxv[r][q] = fdec(mstIn[(long)b * sStat + gm + q]);
                sacc[r][q] = 0.f;
            }
        }
    }

    auto fetchA = [&](int k0) {
#pragma unroll
        for (int r = 0; r < LA; r++) {
            int e = tid + r * 256;
            float4 v = {0.f, 0.f, 0.f, 0.f};
            if (!TAR) {
                int k = e / MV, mq = e - k * MV;
                int gm = m0 + mq * 4;
                if (k0 + k < kend && gm + 3 < M) {
                    v = *(const float4*)(A + (long)(k0 + k) * lda + gm);
                    if (EXPA) {
                        v.x = fexp(v.x - mxv[r][0]); sacc[r][0] += v.x;
                        v.y = fexp(v.y - mxv[r][1]); sacc[r][1] += v.y;
                        v.z = fexp(v.z - mxv[r][2]); sacc[r][2] += v.z;
                        v.w = fexp(v.w - mxv[r][3]); sacc[r][3] += v.w;
                    }
                }
            } else {
                int m = e / 4, kq = e - m * 4;
                int gm = m0 + m, gk = k0 + kq * 4;
                if (gm < M) {
                    if (gk + 3 < kend) {
                        v = *(const float4*)(A + (long)gm * lda + gk);
                    } else {
                        float* vv = (float*)&v;
#pragma unroll
                        for (int q = 0; q < 4; q++)
                            if (gk + q < kend) vv[q] = A[(long)gm * lda + gk + q];
                    }
                }
            }
            ra[r] = v;
        }
    };
    auto storeA = [&](int buf) {
#pragma unroll
        for (int r = 0; r < LA; r++) {
            int e = tid + r * 256;
            if (!TAR) {
                int k = e / MV, mq = e - k * MV;
                *(float4*)&As[buf][k][mq * 4] = ra[r];
            } else {
                int m = e / 4, kq = e - m * 4;
                As[buf][kq * 4 + 0][m] = ra[r].x; As[buf][kq * 4 + 1][m] = ra[r].y;
                As[buf][kq * 4 + 2][m] = ra[r].z; As[buf][kq * 4 + 3][m] = ra[r].w;
            }
        }
    };
    auto fetchB = [&](int k0) {
#pragma unroll
        for (int r = 0; r < LB; r++) {
            int e = tid + r * 256;
            float4 v = {0.f, 0.f, 0.f, 0.f};
            if (!TBR) {
                int k = e / NV, nq = e - k * NV;
                int gn = n0 + nq * 4;
                if (k0 + k < kend && gn + 3 < N) {
                    long flat = (long)(k0 + k) * ldb + gn;
                    v = *(const float4*)(B + flat);
                    if (DIVB) {
                        float iv = sinv[(long)b * sStat + (int)(flat >> 6)];
                        v.x *= iv; v.y *= iv; v.z *= iv; v.w *= iv;
                    }
                }
            } else {
                int n = e / 4, kq = e - n * 4;
                int gn = n0 + n, gk = k0 + kq * 4;
                if (gn < N) {
                    if (gk + 3 < kend) {
                        v = *(const float4*)(B + (long)gn * ldb + gk);
                    } else {
                        float* vv = (float*)&v;
#pragma unroll
                        for (int q = 0; q < 4; q++)
                            if (gk + q < kend) vv[q] = B[(long)gn * ldb + gk + q];
                    }
                }
            }
            rb[r] = v;
        }
    };
    auto storeB = [&](int buf) {
#pragma unroll
        for (int r = 0; r < LB; r++) {
            int e = tid + r * 256;
            if (!TBR) {
                int k = e / NV, nq = e - k * NV;
                *(float4*)&Bs[buf][k][nq * 4] = rb[r];
            } else {
                int n = e / 4, kq = e - n * 4;
                Bs[buf][kq * 4 + 0][n] = rb[r].x; Bs[buf][kq * 4 + 1][n] = rb[r].y;
                Bs[buf][kq * 4 + 2][n] = rb[r].z; Bs[buf][kq * 4 + 3][n] = rb[r].w;
            }
        }
    };

    // accumulators: rows paired (2i, 2i+1) in one 64-bit lane pair
    ull acc2[TM / 2][TN];
#pragma unroll
    for (int i = 0; i < TM / 2; i++)
#pragma unroll
        for (int j = 0; j < TN; j++) acc2[i][j] = 0ULL;

    const int nkt = (kend - kbeg + BK - 1) / BK;

    fetchA(kbeg); fetchB(kbeg);
    storeA(0); storeB(0);
    __syncthreads();

    for (int t = 0; t < nkt; t++) {
        const int cur = t & 1, nxt = cur ^ 1;
        const bool more = (t + 1) < nkt;
        if (more) { fetchA(kbeg + (t + 1) * BK); fetchB(kbeg + (t + 1) * BK); }

#pragma unroll
        for (int kk = 0; kk < BK; kk++) {
            float4 av[TM / 4];
#pragma unroll
            for (int i = 0; i < TM / 4; i++)
                av[i] = *(const float4*)&As[cur][kk][ty * TM + i * 4];
            const ull* a2 = (const ull*)av;   // TM/2 row-pairs

            ull b2[TN];
            if (!TBR) {
                float4 bv[TN / 4];
#pragma unroll
                for (int j = 0; j < TN / 4; j++)
                    bv[j] = *(const float4*)&Bs[cur][kk][tx * TN + j * 4];
                const float* bf = (const float*)bv;
#pragma unroll
                for (int j = 0; j < TN; j++) b2[j] = dup2(bf[j]);
            } else {
#pragma unroll
                for (int j = 0; j < TN; j++) b2[j] = dup2(Bs[cur][kk][tx * TN + j]);
            }

#pragma unroll
            for (int i = 0; i < TM / 2; i++)
#pragma unroll
                for (int j = 0; j < TN; j++)
                    ffma2(acc2[i][j], a2[i], b2[j]);
        }

        if (more) { storeA(nxt); storeB(nxt); }
        __syncthreads();
    }

    // ---- C write ----
#pragma unroll
    for (int i2 = 0; i2 < TM / 2; i2++) {
        int gmA = m0 + ty * TM + 2 * i2;
        int gmB = gmA + 1;
#pragma unroll
        for (int j = 0; j < TN; j++) {
            int gn = n0 + tx * TN + j;
            if (gn >= N) continue;
            float2 w = *(float2*)&acc2[i2][j];
            if (gmA < M) {
                if (ATOM) atomicAdd(&C[(long)gmA * ldc + gn], w.x);
                else      C[(long)gmA * ldc + gn] = w.x;
            }
            if (gmB < M) {
                if (ATOM) atomicAdd(&C[(long)gmB * ldc + gn], w.y);
                else      C[(long)gmB * ldc + gn] = w.y;
            }
        }
    }

    // ---- fused column max (logits) ----
    if (CMAX) {
        float* red = &As[0][0][0];
        float cm[TN];
#pragma unroll
        for (int j = 0; j < TN; j++) {
            float m = -1e30f;
#pragma unroll
            for (int i2 = 0; i2 < TM / 2; i2++) {
                float2 w = *(float2*)&acc2[i2][j];
                m = fmaxf(m, fmaxf(w.x, w.y));
            }
            cm[j] = m;
        }
#pragma unroll
        for (int j = 0; j < TN; j++) red[ty * BN + tx * TN + j] = cm[j];
        __syncthreads();
        if (tid < BN) {
            float m = red[tid];
#pragma unroll
            for (int t = 1; t < TX; t++) m = fmaxf(m, red[t * BN + tid]);
            atomicMax(&mstOut[(long)b * sStat + n0 + tid], fenc(m));
        }
    }

    // ---- fused exp-sum (O-GEMM) ----
    if (EXPA) {
        float* red = &As[0][0][0];
        if (tid < BM) red[tid] = 0.f;
        __syncthreads();
#pragma unroll
        for (int r = 0; r < LA; r++) {
            int e = tid + r * 256;
            int mq = e - (e / MV) * MV;
#pragma unroll
            for (int q = 0; q < 4; q++)
                atomicAdd(&red[mq * 4 + q], sacc[r][q]);
        }
        __syncthreads();
        if (tid < BM)
            atomicAdd(&sumOut[(long)b * sStat + m0 + tid], red[tid]);
    }

    // ---- fused BN partial stats (Z-GEMM) ----
    if (STAT) {
        float* red = &As[0][0][0];
        if (tid < 2 * BM) red[tid] = 0.f;
        __syncthreads();
#pragma unroll
        for (int i2 = 0; i2 < TM / 2; i2++) {
            float sX = 0.f, s2X = 0.f, sY = 0.f, s2Y = 0.f;
#pragma unroll
            for (int j = 0; j < TN; j++) {
                float2 w = *(float2*)&acc2[i2][j];
                sX += w.x; s2X = fmaf(w.x, w.x, s2X);
                sY += w.y; s2Y = fmaf(w.y, w.y, s2Y);
            }
            atomicAdd(&red[ty * TM + 2 * i2],          sX);
            atomicAdd(&red[BM + ty * TM + 2 * i2],     s2X);
            atomicAdd(&red[ty * TM + 2 * i2 + 1],      sY);
            atomicAdd(&red[BM + ty * TM + 2 * i2 + 1], s2Y);
        }
        __syncthreads();
        if (tid < BM && m0 + tid < M) {
            atomicAdd(&statOut[m0 + tid], red[tid]);
            atomicAdd(&statOut[CPc + m0 + tid], red[BM + tid]);
        }
    }
}

// ---------------------------------------------------------------------------
// Small kernels
// ---------------------------------------------------------------------------
__global__ void sinv_k(const float* __restrict__ s, float* __restrict__ si)
{
    int i = blockIdx.x * 256 + threadIdx.x;
    si[i] = 1.0f / s[i];
}

__global__ void bn_finalize_k(const float* __restrict__ stat,
                              float* __restrict__ mean, float* __restrict__ istd)
{
    int c = threadIdx.x;
    const float inv = 1.0f / (float)(NB * NQc);
    float m = stat[c] * inv;
    float v = stat[CPc + c] * inv - m * m;
    mean[c] = m;
    istd[c] = rsqrtf(v + 1e-5f);
}

__global__ void bn_apply_k(const float* __restrict__ Z,
                           const float* __restrict__ mean, const float* __restrict__ istd,
                           const float* __restrict__ gamma, const float* __restrict__ beta,
                           float* __restrict__ out, int first)
{
    long i = ((long)blockIdx.x * 256 + threadIdx.x) * 4;
    int c = (int)((i / NQc) % CPc);
    float a = istd[c] * gamma[c];
    float bb = fmaf(-mean[c], a, beta[c]);
    float4 z = *(const float4*)(Z + i);
    float4 v;
    v.x = fmaf(z.x, a, bb); v.y = fmaf(z.y, a, bb);
    v.z = fmaf(z.z, a, bb); v.w = fmaf(z.w, a, bb);
    if (first) {
        *(float4*)(out + i) = v;
    } else {
        float4 o = *(const float4*)(out + i);
        o.x += v.x; o.y += v.y; o.z += v.z; o.w += v.w;
        *(float4*)(out + i) = o;
    }
}

// ---------------------------------------------------------------------------
// Host launch
// ---------------------------------------------------------------------------
extern "C" void kernel_launch(void* const* d_in, const int* in_sizes, int n_in,
                              void* d_out, int out_size)
{
    (void)in_sizes; (void)n_in; (void)out_size;

    const float* persp = (const float*)d_in[0];
    const float* resp[5] = {
        (const float*)d_in[1], (const float*)d_in[2], (const float*)d_in[3],
        (const float*)d_in[4], (const float*)d_in[5] };
    const float* t_w = (const float*)d_in[6];
    const float* z_w = (const float*)d_in[7];
    float* out = (float*)d_out;

    float *T, *PGw, *PG, *Lt, *O, *Z, *sum, *sinv, *stat, *mean, *istd;
    unsigned* mstU;
    cudaGetSymbolAddress((void**)&T,    g_T);
    cudaGetSymbolAddress((void**)&PGw,  g_PGw);
    cudaGetSymbolAddress((void**)&PG,   g_PG);
    cudaGetSymbolAddress((void**)&Lt,   g_Lt);
    cudaGetSymbolAddress((void**)&O,    g_O);
    cudaGetSymbolAddress((void**)&Z,    g_Z);
    cudaGetSymbolAddress((void**)&mstU, g_mstU);
    cudaGetSymbolAddress((void**)&sum,  g_sum);
    cudaGetSymbolAddress((void**)&sinv, g_sinv);
    cudaGetSymbolAddress((void**)&stat, g_stat);
    cudaGetSymbolAddress((void**)&mean, g_mean);
    cudaGetSymbolAddress((void**)&istd, g_istd);

    // ---- T = t_w[64,256] @ persp ----
    gemm_k<64, 128, 4, 8, true, false, false, false, false, false, false>
        <<<dim3(NQc / 128, 1, NB), 256>>>(
            t_w, persp, T, PLc, NQc, CPc, CPc, NQc, NQc,
            0L, (long)CPc * NQc, (long)PLc * NQc, 1, CPc,
            nullptr, nullptr, nullptr, nullptr, nullptr, 0);

    static const int OKS[5] = {8, 8, 4, 2, 1};

    for (int i = 0; i < 5; i++) {
        const int Cr = CRs[i];
        const int Mi = Ms[i];
        const float* p_w   = (const float*)d_in[8  + 4 * i];
        const float* g_wt  = (const float*)d_in[9  + 4 * i];
        const float* gamma = (const float*)d_in[10 + 4 * i];
        const float* beta  = (const float*)d_in[11 + 4 * i];

        cudaMemcpyAsync(PGw,            p_w, (size_t)PLc * Cr * 4,
                        cudaMemcpyDeviceToDevice, 0);
        cudaMemcpyAsync(PGw + PLc * Cr, g_wt, (size_t)PLc * Cr * 4,
                        cudaMemcpyDeviceToDevice, 0);

        // ---- PG = PGw[128,Cr] @ resp  (split-K chunk 128) ----
        {
            int ks = Cr >= 128 ? Cr / 128 : 1;
            int kchunk = Cr / ks;
            dim3 grid((Mi + 127) / 128, 1, NB * ks);
            if (ks > 1) {
                cudaMemsetAsync(PG, 0, (size_t)NB * 128 * Mi * 4, 0);
                gemm_k<128, 128, 8, 8, true, false, false, false, false, false, true>
                    <<<grid, 256>>>(PGw, resp[i], PG, 128, Mi, Cr, Cr, Mi, Mi,
                                    0L, (long)Cr * Mi, (long)128 * Mi, ks, kchunk,
                                    nullptr, nullptr, nullptr, nullptr, nullptr, 0);
            } else {
                gemm_k<128, 128, 8, 8, true, false, false, false, false, false, false>
                    <<<grid, 256>>>(PGw, resp[i], PG, 128, Mi, Cr, Cr, Mi, Mi,
                                    0L, (long)Cr * Mi, (long)128 * Mi, 1, Cr,
                                    nullptr, nullptr, nullptr, nullptr, nullptr, 0);
            }
        }

        // ---- Lt = P^T @ T with fused column max ----
        cudaMemsetAsync(mstU, 0, (size_t)NB * NQc * 4, 0);
        {
            dim3 grid(NQc / 128, (Mi + 127) / 128, NB);
            gemm_k<128, 128, 8, 8, false, false, false, true, false, false, false>
                <<<grid, 256>>>(PG, T, Lt, Mi, NQc, PLc, Mi, NQc, NQc,
                                (long)128 * Mi, (long)PLc * NQc, (long)Mi * NQc,
                                1, PLc,
                                nullptr, mstU, nullptr, nullptr, nullptr, NQc);
        }

        // ---- O = exp(Lt - max)^T @ G^T  (fused exp-sum; split-K) ----
        cudaMemsetAsync(sum, 0, (size_t)NB * NQc * 4, 0);
        {
            int ks = OKS[i];
            int kchunk = (Mi + ks - 1) / ks;
            dim3 grid(1, NQc / 128, NB * ks);
            if (ks > 1) {
                cudaMemsetAsync(O, 0, (size_t)NB * NQc * PLc * 4, 0);
                gemm_k<128, 64, 8, 4, false, true, true, false, false, false, true>
                    <<<grid, 256>>>(Lt, PG + (long)PLc * Mi, O, NQc, PLc, Mi,
                                    NQc, Mi, PLc,
                                    (long)Mi * NQc, (long)128 * Mi, (long)NQc * PLc,
                                    ks, kchunk,
                                    mstU, nullptr, sum, nullptr, nullptr, NQc);
            } else {
                gemm_k<128, 64, 8, 4, false, true, true, false, false, false, false>
                    <<<grid, 256>>>(Lt, PG + (long)PLc * Mi, O, NQc, PLc, Mi,
                                    NQc, Mi, PLc,
                                    (long)Mi * NQc, (long)128 * Mi, (long)NQc * PLc,
                                    1, Mi,
                                    mstU, nullptr, sum, nullptr, nullptr, NQc);
            }
        }
        sinv_k<<<NB * NQc / 256, 256>>>(sum, sinv);

        // ---- Z = z_w @ (O/sum)_view with fused BN stats ----
        cudaMemsetAsync(stat, 0, (size_t)2 * CPc * 4, 0);
        {
            dim3 grid(NQc / 128, CPc / 128, NB);
            gemm_k<128, 128, 8, 8, true, false, false, false, true, true, false>
                <<<grid, 256>>>(z_w, O, Z, CPc, NQc, PLc, PLc, NQc, NQc,
                                0L, (long)NQc * PLc, (long)CPc * NQc, 1, PLc,
                                nullptr, nullptr, nullptr, sinv, stat, NQc);
        }

        bn_finalize_k<<<1, 256>>>(stat, mean, istd);
        {
            long total4 = (long)NB * CPc * NQc / 4;
            bn_apply_k<<<(unsigned)(total4 / 256), 256>>>(
                Z, mean, istd, gamma, beta, out, i == 0 ? 1 : 0);
        }
    }
}

// round 7
// speedup vs baseline: 1.1834x; 1.1834x over previous
#include <cuda_runtime.h>
#include <math.h>

#define NB   4
#define CPc  256
#define PLc  64
#define NQc  2304

static const int CRs[5] = {64, 256, 512, 1024, 2048};
static const int Ms [5] = {2304, 2304, 576, 144, 36};

typedef unsigned long long ull;

// ---------------------------------------------------------------------------
// Scratch
// ---------------------------------------------------------------------------
__device__ float g_T  [NB * PLc * NQc];
__device__ float g_PGw[2 * PLc * 2048];
__device__ float g_PG [NB * 2 * PLc * NQc];
__device__ float g_O  [NB * NQc * PLc];
__device__ float g_Z  [NB * CPc * NQc];
__device__ float g_stat[2 * CPc];
__device__ float g_mean[CPc];
__device__ float g_istd[CPc];

// ---------------------------------------------------------------------------
// Helpers
// ---------------------------------------------------------------------------
__device__ __forceinline__ float fexp(float x)
{
    // CLAMP: magic-number range reduction is only valid for moderate |x|.
    // All call sites have x <= 0; exp(-87) ~ 1e-38 ~ 0, so this is exact.
    x = fmaxf(x, -87.0f);
    const float L2E = 1.4426950408889634f;
    float t = fmaf(x, L2E, 12582912.0f);
    float n = t - 12582912.0f;
    float f = fmaf(x, L2E, -n);
    float p = 1.33335581e-3f;
    p = fmaf(p, f, 9.61812911e-3f);
    p = fmaf(p, f, 5.55041087e-2f);
    p = fmaf(p, f, 2.40226507e-1f);
    p = fmaf(p, f, 6.93147180e-1f);
    p = fmaf(p, f, 1.0f);
    int ni = (int)n;
    ni = max(-126, min(127, ni));
    return p * __int_as_float((ni + 127) << 23);
}

__device__ __forceinline__ void ffma2(ull& c, ull a, ull b)
{
    asm("fma.rn.f32x2 %0, %1, %2, %0;" : "+l"(c) : "l"(a), "l"(b));
}
__device__ __forceinline__ void fmul2(ull& c, ull b)
{
    asm("mul.rn.f32x2 %0, %0, %1;" : "+l"(c) : "l"(b));
}
__device__ __forceinline__ ull dup2(float x)
{
    ull r;
    unsigned u = __float_as_uint(x);
    asm("mov.b64 %0, {%1, %1};" : "=l"(r) : "r"(u));
    return r;
}
__device__ __forceinline__ ull pack2(float lo, float hi)
{
    ull r;
    asm("mov.b64 %0, {%1, %2};" : "=l"(r) : "f"(lo), "f"(hi));
    return r;
}

// ---------------------------------------------------------------------------
// Flash attention: one block = 64 queries; loop over m-tiles of 64.
//   S[q][m] = sum_k T[k][q] * P[k][m]        (K = 64)
//   online softmax over m; O[q][c] += Ptilde @ G ; epilogue /= sum.
// Thread grid 16(ty: 4 q each) x 16(tx: 4 m / 4 c each). FFMA2 paired on q.
// ---------------------------------------------------------------------------
__global__ void __launch_bounds__(256) flash_k(
    const float* __restrict__ T, const float* __restrict__ PG,
    float* __restrict__ O, int Mi)
{
    extern __shared__ float sm[];
    float (*Tq)[64] = (float(*)[64])(sm);            //  4096 f
    float (*Ps)[64] = (float(*)[64])(sm + 4096);     //  4096 f
    float (*Gs)[68] = (float(*)[68])(sm + 8192);     //  4352 f
    float (*Pt)[68] = (float(*)[68])(sm + 12544);    //  4352 f

    const int b  = blockIdx.y;
    const int n0 = blockIdx.x * 64;
    const int tid = threadIdx.x;
    const int ty = tid >> 4, tx = tid & 15;

    const float* Tb = T + (long)b * PLc * NQc;
    const float* Pb = PG + (long)b * 2 * PLc * Mi;      // rows 0..63 : P[k][m]
    const float* Gb = Pb + (long)PLc * Mi;              // rows 0..63 : G[c][m]

    // load Tq[k][q]
#pragma unroll
    for (int r = 0; r < 4; r++) {
        int e = (tid + r * 256) * 4;
        int k = e >> 6, q = e & 63;
        *(float4*)&Tq[k][q] = *(const float4*)(Tb + (long)k * NQc + n0 + q);
    }

    float Mrun[4], Srun[4];
#pragma unroll
    for (int q = 0; q < 4; q++) { Mrun[q] = -1e30f; Srun[q] = 0.f; }
    ull acco[2][4];
#pragma unroll
    for (int i = 0; i < 2; i++)
#pragma unroll
        for (int j = 0; j < 4; j++) acco[i][j] = 0ULL;

    for (int m0 = 0; m0 < Mi; m0 += 64) {
        // ---- load P tile (K-major) and G tile (transposed) ----
#pragma unroll
        for (int r = 0; r < 4; r++) {
            int e = (tid + r * 256) * 4;
            int k = e >> 6, mm = e & 63;
            float4 v = {0.f, 0.f, 0.f, 0.f};
            if (m0 + mm < Mi) v = *(const float4*)(Pb + (long)k * Mi + m0 + mm);
            *(float4*)&Ps[k][mm] = v;
        }
#pragma unroll
        for (int r = 0; r < 4; r++) {
            int e = tid + r * 256;          // 1024 quads
            int c = e >> 4, mq = (e & 15) * 4;
            float4 v = {0.f, 0.f, 0.f, 0.f};
            if (m0 + mq < Mi) v = *(const float4*)(Gb + (long)c * Mi + m0 + mq);
            Gs[mq + 0][c] = v.x; Gs[mq + 1][c] = v.y;
            Gs[mq + 2][c] = v.z; Gs[mq + 3][c] = v.w;
        }
        __syncthreads();

        // ---- S GEMM ----
        ull accs[2][4];
#pragma unroll
        for (int i = 0; i < 2; i++)
#pragma unroll
            for (int j = 0; j < 4; j++) accs[i][j] = 0ULL;

#pragma unroll 16
        for (int kk = 0; kk < 64; kk++) {
            float4 a = *(const float4*)&Tq[kk][ty * 4];
            const ull* a2 = (const ull*)&a;
            float4 bv = *(const float4*)&Ps[kk][tx * 4];
            const float* bf = (const float*)&bv;
#pragma unroll
            for (int j = 0; j < 4; j++) {
                ull bd = dup2(bf[j]);
                ffma2(accs[0][j], a2[0], bd);
                ffma2(accs[1][j], a2[1], bd);
            }
        }

        // ---- extract S, online stats ----
        float S[4][4];
#pragma unroll
        for (int qp = 0; qp < 2; qp++)
#pragma unroll
            for (int j = 0; j < 4; j++) {
                float2 w = *(float2*)&accs[qp][j];
                S[2 * qp][j] = w.x;
                S[2 * qp + 1][j] = w.y;
            }

        float tm[4];
#pragma unroll
        for (int q = 0; q < 4; q++) {
            tm[q] = fmaxf(fmaxf(S[q][0], S[q][1]), fmaxf(S[q][2], S[q][3]));
        }
#pragma unroll
        for (int s = 1; s < 16; s <<= 1) {
#pragma unroll
            for (int q = 0; q < 4; q++)
                tm[q] = fmaxf(tm[q], __shfl_xor_sync(0xFFFFFFFFu, tm[q], s));
        }

        float f[4], ls[4];
#pragma unroll
        for (int q = 0; q < 4; q++) {
            float Mn = fmaxf(Mrun[q], tm[q]);
            f[q] = fexp(Mrun[q] - Mn);
            Mrun[q] = Mn;
            ls[q] = 0.f;
        }

#pragma unroll
        for (int j = 0; j < 4; j++) {
            bool ok = (m0 + tx * 4 + j) < Mi;
#pragma unroll
            for (int q = 0; q < 4; q++) {
                float p = ok ? fexp(S[q][j] - Mrun[q]) : 0.f;
                S[q][j] = p;
                ls[q] += p;
            }
        }
#pragma unroll
        for (int s = 1; s < 16; s <<= 1) {
#pragma unroll
            for (int q = 0; q < 4; q++)
                ls[q] += __shfl_xor_sync(0xFFFFFFFFu, ls[q], s);
        }
#pragma unroll
        for (int q = 0; q < 4; q++)
            Srun[q] = fmaf(Srun[q], f[q], ls[q]);

        // rescale O accumulators
        ull f01 = pack2(f[0], f[1]);
        ull f23 = pack2(f[2], f[3]);
#pragma unroll
        for (int j = 0; j < 4; j++) { fmul2(acco[0][j], f01); fmul2(acco[1][j], f23); }

        // write exp'd tile Pt[m][q]
#pragma unroll
        for (int j = 0; j < 4; j++) {
            float4 v = {S[0][j], S[1][j], S[2][j], S[3][j]};
            *(float4*)&Pt[tx * 4 + j][ty * 4] = v;
        }
        __syncthreads();

        // ---- O GEMM: O[q][c] += Pt[m][q] * Gs[m][c] ----
#pragma unroll 16
        for (int mm = 0; mm < 64; mm++) {
            float4 a = *(const float4*)&Pt[mm][ty * 4];
            const ull* a2 = (const ull*)&a;
            float4 bv = *(const float4*)&Gs[mm][tx * 4];
            const float* bf = (const float*)&bv;
#pragma unroll
            for (int j = 0; j < 4; j++) {
                ull bd = dup2(bf[j]);
                ffma2(acco[0][j], a2[0], bd);
                ffma2(acco[1][j], a2[1], bd);
            }
        }
        __syncthreads();
    }

    // ---- epilogue: normalize, store ----
    float inv[4];
#pragma unroll
    for (int q = 0; q < 4; q++) inv[q] = 1.0f / Srun[q];
#pragma unroll
    for (int q = 0; q < 4; q++) {
        float4 v;
        float* vv = (float*)&v;
#pragma unroll
        for (int j = 0; j < 4; j++) {
            float2 w = *(float2*)&acco[q >> 1][j];
            vv[j] = ((q & 1) ? w.y : w.x) * inv[q];
        }
        *(float4*)(O + ((long)b * NQc + n0 + ty * 4 + q) * PLc + tx * 4) = v;
    }
}

// ---------------------------------------------------------------------------
// Tiled SGEMM (FFMA2, double-buffered) for T / PG / Z. STAT fuses BN partials.
// ---------------------------------------------------------------------------
template<int BM, int BN, int TM, int TN, bool TAR, bool TBR, bool STAT, bool ATOM>
__global__ void __launch_bounds__(256) gemm_k(
    const float* __restrict__ A, const float* __restrict__ B, float* __restrict__ C,
    int M, int N, int K, int lda, int ldb, int ldc,
    long sA, long sB, long sC, int ksplit, int kchunk,
    float* __restrict__ statOut)
{
    constexpr int BK = 16;
    constexpr int LA = BM * BK / 1024;
    constexpr int LB = BN * BK / 1024;
    constexpr int MV = BM / 4, NV = BN / 4;
    constexpr int TX = BN / TN;
    static_assert((BM / TM) * (BN / TN) == 256, "256 threads");
    static_assert(TM % 2 == 0, "TM even");

    __shared__ float As[2][BK][BM];
    __shared__ float Bs[2][BK][BN + (TBR ? 1 : 0)];

    const int b  = blockIdx.z / ksplit;
    const int kz = blockIdx.z - b * ksplit;
    A += (long)b * sA;  B += (long)b * sB;  C += (long)b * sC;

    const int kbeg = kz * kchunk;
    const int kend = min(K, kbeg + kchunk);
    const int m0 = blockIdx.y * BM, n0 = blockIdx.x * BN;
    const int tid = threadIdx.x;
    const int ty = tid / TX, tx = tid - ty * TX;

    float4 ra[LA], rb[LB];

    auto fetchA = [&](int k0) {
#pragma unroll
        for (int r = 0; r < LA; r++) {
            int e = tid + r * 256;
            float4 v = {0.f, 0.f, 0.f, 0.f};
            if (!TAR) {
                int k = e / MV, mq = e - k * MV;
                int gm = m0 + mq * 4;
                if (k0 + k < kend && gm + 3 < M)
                    v = *(const float4*)(A + (long)(k0 + k) * lda + gm);
            } else {
                int m = e / 4, kq = e - m * 4;
                int gm = m0 + m, gk = k0 + kq * 4;
                if (gm < M) {
                    if (gk + 3 < kend) {
                        v = *(const float4*)(A + (long)gm * lda + gk);
                    } else {
                        float* vv = (float*)&v;
#pragma unroll
                        for (int q = 0; q < 4; q++)
                            if (gk + q < kend) vv[q] = A[(long)gm * lda + gk + q];
                    }
                }
            }
            ra[r] = v;
        }
    };
    auto storeA = [&](int buf) {
#pragma unroll
        for (int r = 0; r < LA; r++) {
            int e = tid + r * 256;
            if (!TAR) {
                int k = e / MV, mq = e - k * MV;
                *(float4*)&As[buf][k][mq * 4] = ra[r];
            } else {
                int m = e / 4, kq = e - m * 4;
                As[buf][kq * 4 + 0][m] = ra[r].x; As[buf][kq * 4 + 1][m] = ra[r].y;
                As[buf][kq * 4 + 2][m] = ra[r].z; As[buf][kq * 4 + 3][m] = ra[r].w;
            }
        }
    };
    auto fetchB = [&](int k0) {
#pragma unroll
        for (int r = 0; r < LB; r++) {
            int e = tid + r * 256;
            float4 v = {0.f, 0.f, 0.f, 0.f};
            if (!TBR) {
                int k = e / NV, nq = e - k * NV;
                int gn = n0 + nq * 4;
                if (k0 + k < kend && gn + 3 < N)
                    v = *(const float4*)(B + (long)(k0 + k) * ldb + gn);
            } else {
                int n = e / 4, kq = e - n * 4;
                int gn = n0 + n, gk = k0 + kq * 4;
                if (gn < N) {
                    if (gk + 3 < kend) {
                        v = *(const float4*)(B + (long)gn * ldb + gk);
                    } else {
                        float* vv = (float*)&v;
#pragma unroll
                        for (int q = 0; q < 4; q++)
                            if (gk + q < kend) vv[q] = B[(long)gn * ldb + gk + q];
                    }
                }
            }
            rb[r] = v;
        }
    };
    auto storeB = [&](int buf) {
#pragma unroll
        for (int r = 0; r < LB; r++) {
            int e = tid + r * 256;
            if (!TBR) {
                int k = e / NV, nq = e - k * NV;
                *(float4*)&Bs[buf][k][nq * 4] = rb[r];
            } else {
                int n = e / 4, kq = e - n * 4;
                Bs[buf][kq * 4 + 0][n] = rb[r].x; Bs[buf][kq * 4 + 1][n] = rb[r].y;
                Bs[buf][kq * 4 + 2][n] = rb[r].z; Bs[buf][kq * 4 + 3][n] = rb[r].w;
            }
        }
    };

    ull acc2[TM / 2][TN];
#pragma unroll
    for (int i = 0; i < TM / 2; i++)
#pragma unroll
        for (int j = 0; j < TN; j++) acc2[i][j] = 0ULL;

    const int nkt = (kend - kbeg + BK - 1) / BK;

    fetchA(kbeg); fetchB(kbeg);
    storeA(0); storeB(0);
    __syncthreads();

    for (int t = 0; t < nkt; t++) {
        const int cur = t & 1, nxt = cur ^ 1;
        const bool more = (t + 1) < nkt;
        if (more) { fetchA(kbeg + (t + 1) * BK); fetchB(kbeg + (t + 1) * BK); }

#pragma unroll
        for (int kk = 0; kk < BK; kk++) {
            float4 av[TM / 4];
#pragma unroll
            for (int i = 0; i < TM / 4; i++)
                av[i] = *(const float4*)&As[cur][kk][ty * TM + i * 4];
            const ull* a2 = (const ull*)av;

            ull b2[TN];
            if (!TBR) {
                float4 bv[TN / 4];
#pragma unroll
                for (int j = 0; j < TN / 4; j++)
                    bv[j] = *(const float4*)&Bs[cur][kk][tx * TN + j * 4];
                const float* bf = (const float*)bv;
#pragma unroll
                for (int j = 0; j < TN; j++) b2[j] = dup2(bf[j]);
            } else {
#pragma unroll
                for (int j = 0; j < TN; j++) b2[j] = dup2(Bs[cur][kk][tx * TN + j]);
            }

#pragma unroll
            for (int i = 0; i < TM / 2; i++)
#pragma unroll
                for (int j = 0; j < TN; j++)
                    ffma2(acc2[i][j], a2[i], b2[j]);
        }

        if (more) { storeA(nxt); storeB(nxt); }
        __syncthreads();
    }

#pragma unroll
    for (int i2 = 0; i2 < TM / 2; i2++) {
        int gmA = m0 + ty * TM + 2 * i2;
        int gmB = gmA + 1;
#pragma unroll
        for (int j = 0; j < TN; j++) {
            int gn = n0 + tx * TN + j;
            if (gn >= N) continue;
            float2 w = *(float2*)&acc2[i2][j];
            if (gmA < M) {
                if (ATOM) atomicAdd(&C[(long)gmA * ldc + gn], w.x);
                else      C[(long)gmA * ldc + gn] = w.x;
            }
            if (gmB < M) {
                if (ATOM) atomicAdd(&C[(long)gmB * ldc + gn], w.y);
                else      C[(long)gmB * ldc + gn] = w.y;
            }
        }
    }

    if (STAT) {
        float* red = &As[0][0][0];
        if (tid < 2 * BM) red[tid] = 0.f;
        __syncthreads();
#pragma unroll
        for (int i2 = 0; i2 < TM / 2; i2++) {
            float sX = 0.f, s2X = 0.f, sY = 0.f, s2Y = 0.f;
#pragma unroll
            for (int j = 0; j < TN; j++) {
                float2 w = *(float2*)&acc2[i2][j];
                sX += w.x; s2X = fmaf(w.x, w.x, s2X);
                sY += w.y; s2Y = fmaf(w.y, w.y, s2Y);
            }
            atomicAdd(&red[ty * TM + 2 * i2],          sX);
            atomicAdd(&red[BM + ty * TM + 2 * i2],     s2X);
            atomicAdd(&red[ty * TM + 2 * i2 + 1],      sY);
            atomicAdd(&red[BM + ty * TM + 2 * i2 + 1], s2Y);
        }
        __syncthreads();
        if (tid < BM && m0 + tid < M) {
            atomicAdd(&statOut[m0 + tid], red[tid]);
            atomicAdd(&statOut[CPc + m0 + tid], red[BM + tid]);
        }
    }
}

// ---------------------------------------------------------------------------
// BN finalize + apply
// ---------------------------------------------------------------------------
__global__ void bn_finalize_k(const float* __restrict__ stat,
                              float* __restrict__ mean, float* __restrict__ istd)
{
    int c = threadIdx.x;
    const float inv = 1.0f / (float)(NB * NQc);
    float m = stat[c] * inv;
    float v = stat[CPc + c] * inv - m * m;
    mean[c] = m;
    istd[c] = rsqrtf(v + 1e-5f);
}

__global__ void bn_apply_k(const float* __restrict__ Z,
                           const float* __restrict__ mean, const float* __restrict__ istd,
                           const float* __restrict__ gamma, const float* __restrict__ beta,
                           float* __restrict__ out, int first)
{
    long i = ((long)blockIdx.x * 256 + threadIdx.x) * 4;
    int c = (int)((i / NQc) % CPc);
    float a = istd[c] * gamma[c];
    float bb = fmaf(-mean[c], a, beta[c]);
    float4 z = *(const float4*)(Z + i);
    float4 v;
    v.x = fmaf(z.x, a, bb); v.y = fmaf(z.y, a, bb);
    v.z = fmaf(z.z, a, bb); v.w = fmaf(z.w, a, bb);
    if (first) {
        *(float4*)(out + i) = v;
    } else {
        float4 o = *(const float4*)(out + i);
        o.x += v.x; o.y += v.y; o.z += v.z; o.w += v.w;
        *(float4*)(out + i) = o;
    }
}

// ---------------------------------------------------------------------------
// Host launch
// ---------------------------------------------------------------------------
extern "C" void kernel_launch(void* const* d_in, const int* in_sizes, int n_in,
                              void* d_out, int out_size)
{
    (void)in_sizes; (void)n_in; (void)out_size;

    const float* persp = (const float*)d_in[0];
    const float* resp[5] = {
        (const float*)d_in[1], (const float*)d_in[2], (const float*)d_in[3],
        (const float*)d_in[4], (const float*)d_in[5] };
    const float* t_w = (const float*)d_in[6];
    const float* z_w = (const float*)d_in[7];
    float* out = (float*)d_out;

    float *T, *PGw, *PG, *O, *Z, *stat, *mean, *istd;
    cudaGetSymbolAddress((void**)&T,    g_T);
    cudaGetSymbolAddress((void**)&PGw,  g_PGw);
    cudaGetSymbolAddress((void**)&PG,   g_PG);
    cudaGetSymbolAddress((void**)&O,    g_O);
    cudaGetSymbolAddress((void**)&Z,    g_Z);
    cudaGetSymbolAddress((void**)&stat, g_stat);
    cudaGetSymbolAddress((void**)&mean, g_mean);
    cudaGetSymbolAddress((void**)&istd, g_istd);

    const int FLASH_SMEM = 16896 * 4;   // 67584 bytes
    cudaFuncSetAttribute(flash_k,
        cudaFuncAttributeMaxDynamicSharedMemorySize, FLASH_SMEM);

    // ---- T = t_w[64,256] @ persp ----
    gemm_k<64, 128, 4, 8, true, false, false, false>
        <<<dim3(NQc / 128, 1, NB), 256>>>(
            t_w, persp, T, PLc, NQc, CPc, CPc, NQc, NQc,
            0L, (long)CPc * NQc, (long)PLc * NQc, 1, CPc, nullptr);

    for (int i = 0; i < 5; i++) {
        const int Cr = CRs[i];
        const int Mi = Ms[i];
        const float* p_w   = (const float*)d_in[8  + 4 * i];
        const float* g_wt  = (const float*)d_in[9  + 4 * i];
        const float* gamma = (const float*)d_in[10 + 4 * i];
        const float* beta  = (const float*)d_in[11 + 4 * i];

        cudaMemcpyAsync(PGw,            p_w, (size_t)PLc * Cr * 4,
                        cudaMemcpyDeviceToDevice, 0);
        cudaMemcpyAsync(PGw + PLc * Cr, g_wt, (size_t)PLc * Cr * 4,
                        cudaMemcpyDeviceToDevice, 0);

        // ---- PG = PGw[128,Cr] @ resp  (split-K chunk 128) ----
        {
            int ks = Cr >= 128 ? Cr / 128 : 1;
            int kchunk = Cr / ks;
            dim3 grid((Mi + 127) / 128, 1, NB * ks);
            if (ks > 1) {
                cudaMemsetAsync(PG, 0, (size_t)NB * 128 * Mi * 4, 0);
                gemm_k<128, 128, 8, 8, true, false, false, true>
                    <<<grid, 256>>>(PGw, resp[i], PG, 128, Mi, Cr, Cr, Mi, Mi,
                                    0L, (long)Cr * Mi, (long)128 * Mi, ks, kchunk,
                                    nullptr);
            } else {
                gemm_k<128, 128, 8, 8, true, false, false, false>
                    <<<grid, 256>>>(PGw, resp[i], PG, 128, Mi, Cr, Cr, Mi, Mi,
                                    0L, (long)Cr * Mi, (long)128 * Mi, 1, Cr,
                                    nullptr);
            }
        }

        // ---- fused attention (logits + softmax + O) ----
        flash_k<<<dim3(NQc / 64, NB), 256, FLASH_SMEM>>>(T, PG, O, Mi);

        // ---- Z = z_w @ O_view with fused BN stats ----
        cudaMemsetAsync(stat, 0, (size_t)2 * CPc * 4, 0);
        {
            dim3 grid(NQc / 128, CPc / 128, NB);
            gemm_k<128, 128, 8, 8, true, false, true, false>
                <<<grid, 256>>>(z_w, O, Z, CPc, NQc, PLc, PLc, NQc, NQc,
                                0L, (long)NQc * PLc, (long)CPc * NQc, 1, PLc,
                                stat);
        }

        bn_finalize_k<<<1, 256>>>(stat, mean, istd);
        {
            long total4 = (long)NB * CPc * NQc / 4;
            bn_apply_k<<<(unsigned)(total4 / 256), 256>>>(
                Z, mean, istd, gamma, beta, out, i == 0 ? 1 : 0);
        }
    }
}

// round 8
// speedup vs baseline: 1.3024x; 1.1006x over previous
#include <cuda_runtime.h>
#include <math.h>

#define NB   4
#define CPc  256
#define PLc  64
#define NQc  2304

static const int CRs[5] = {64, 256, 512, 1024, 2048};

typedef unsigned long long ull;

// per-scale M sizes and PG offsets (floats), compile-time
__constant__ int  d_Mi[5]    = {2304, 2304, 576, 144, 36};
__constant__ long d_PGoff[5] = {0L,
                                (long)NB * 128 * 2304,
                                (long)NB * 128 * (2304 + 2304),
                                (long)NB * 128 * (2304 + 2304 + 576),
                                (long)NB * 128 * (2304 + 2304 + 576 + 144)};
#define PG_TOTAL ((long)NB * 128 * (2304 + 2304 + 576 + 144 + 36))
#define OSZ ((long)NB * NQc * PLc)
#define ZSZ ((long)NB * CPc * NQc)

// ---------------------------------------------------------------------------
// Scratch
// ---------------------------------------------------------------------------
__device__ float g_T  [NB * PLc * NQc];
__device__ float g_PGw[2 * PLc * (64 + 256 + 512 + 1024 + 2048)];
__device__ float g_PG [NB * 128 * (2304 + 2304 + 576 + 144 + 36)];
__device__ float g_O  [5 * NB * NQc * PLc];
__device__ float g_Z  [5 * NB * CPc * NQc];
__device__ float g_stat[5 * 2 * CPc];
__device__ float g_mean[5 * CPc];
__device__ float g_istd[5 * CPc];

// ---------------------------------------------------------------------------
// Helpers
// ---------------------------------------------------------------------------
__device__ __forceinline__ float fexp(float x)
{
    x = fmaxf(x, -87.0f);                 // keep magic-number reduction in range
    const float L2E = 1.4426950408889634f;
    float t = fmaf(x, L2E, 12582912.0f);
    float n = t - 12582912.0f;
    float f = fmaf(x, L2E, -n);
    float p = 1.33335581e-3f;
    p = fmaf(p, f, 9.61812911e-3f);
    p = fmaf(p, f, 5.55041087e-2f);
    p = fmaf(p, f, 2.40226507e-1f);
    p = fmaf(p, f, 6.93147180e-1f);
    p = fmaf(p, f, 1.0f);
    int ni = (int)n;
    ni = max(-126, min(127, ni));
    return p * __int_as_float((ni + 127) << 23);
}

__device__ __forceinline__ void ffma2(ull& c, ull a, ull b)
{
    asm("fma.rn.f32x2 %0, %1, %2, %0;" : "+l"(c) : "l"(a), "l"(b));
}
__device__ __forceinline__ void fmul2(ull& c, ull b)
{
    asm("mul.rn.f32x2 %0, %0, %1;" : "+l"(c) : "l"(b));
}
__device__ __forceinline__ ull dup2(float x)
{
    ull r;
    unsigned u = __float_as_uint(x);
    asm("mov.b64 %0, {%1, %1};" : "=l"(r) : "r"(u));
    return r;
}
__device__ __forceinline__ ull pack2(float lo, float hi)
{
    ull r;
    asm("mov.b64 %0, {%1, %2};" : "=l"(r) : "f"(lo), "f"(hi));
    return r;
}

// ---------------------------------------------------------------------------
// Merged flash attention over ALL scales: blockIdx.y = scale*NB + b.
// ---------------------------------------------------------------------------
__global__ void __launch_bounds__(256) flash_k(
    const float* __restrict__ T, const float* __restrict__ PG,
    float* __restrict__ O)
{
    extern __shared__ float sm[];
    float (*Tq)[64] = (float(*)[64])(sm);
    float (*Ps)[64] = (float(*)[64])(sm + 4096);
    float (*Gs)[68] = (float(*)[68])(sm + 8192);
    float (*Pt)[68] = (float(*)[68])(sm + 12544);

    const int sc = blockIdx.y >> 2;          // NB == 4
    const int b  = blockIdx.y & 3;
    const int Mi = d_Mi[sc];
    const int n0 = blockIdx.x * 64;
    const int tid = threadIdx.x;
    const int ty = tid >> 4, tx = tid & 15;

    const float* Tb = T + (long)b * PLc * NQc;
    const float* Pb = PG + d_PGoff[sc] + (long)b * 2 * PLc * Mi;
    const float* Gb = Pb + (long)PLc * Mi;
    float* Ob = O + (long)sc * OSZ + (long)b * NQc * PLc;

#pragma unroll
    for (int r = 0; r < 4; r++) {
        int e = (tid + r * 256) * 4;
        int k = e >> 6, q = e & 63;
        *(float4*)&Tq[k][q] = *(const float4*)(Tb + (long)k * NQc + n0 + q);
    }

    float Mrun[4], Srun[4];
#pragma unroll
    for (int q = 0; q < 4; q++) { Mrun[q] = -1e30f; Srun[q] = 0.f; }
    ull acco[2][4];
#pragma unroll
    for (int i = 0; i < 2; i++)
#pragma unroll
        for (int j = 0; j < 4; j++) acco[i][j] = 0ULL;

    for (int m0 = 0; m0 < Mi; m0 += 64) {
#pragma unroll
        for (int r = 0; r < 4; r++) {
            int e = (tid + r * 256) * 4;
            int k = e >> 6, mm = e & 63;
            float4 v = {0.f, 0.f, 0.f, 0.f};
            if (m0 + mm < Mi) v = *(const float4*)(Pb + (long)k * Mi + m0 + mm);
            *(float4*)&Ps[k][mm] = v;
        }
#pragma unroll
        for (int r = 0; r < 4; r++) {
            int e = tid + r * 256;
            int c = e >> 4, mq = (e & 15) * 4;
            float4 v = {0.f, 0.f, 0.f, 0.f};
            if (m0 + mq < Mi) v = *(const float4*)(Gb + (long)c * Mi + m0 + mq);
            Gs[mq + 0][c] = v.x; Gs[mq + 1][c] = v.y;
            Gs[mq + 2][c] = v.z; Gs[mq + 3][c] = v.w;
        }
        __syncthreads();

        ull accs[2][4];
#pragma unroll
        for (int i = 0; i < 2; i++)
#pragma unroll
            for (int j = 0; j < 4; j++) accs[i][j] = 0ULL;

#pragma unroll 16
        for (int kk = 0; kk < 64; kk++) {
            float4 a = *(const float4*)&Tq[kk][ty * 4];
            const ull* a2 = (const ull*)&a;
            float4 bv = *(const float4*)&Ps[kk][tx * 4];
            const float* bf = (const float*)&bv;
#pragma unroll
            for (int j = 0; j < 4; j++) {
                ull bd = dup2(bf[j]);
                ffma2(accs[0][j], a2[0], bd);
                ffma2(accs[1][j], a2[1], bd);
            }
        }

        float S[4][4];
#pragma unroll
        for (int qp = 0; qp < 2; qp++)
#pragma unroll
            for (int j = 0; j < 4; j++) {
                float2 w = *(float2*)&accs[qp][j];
                S[2 * qp][j] = w.x;
                S[2 * qp + 1][j] = w.y;
            }

        float tm[4];
#pragma unroll
        for (int q = 0; q < 4; q++)
            tm[q] = fmaxf(fmaxf(S[q][0], S[q][1]), fmaxf(S[q][2], S[q][3]));
#pragma unroll
        for (int s = 1; s < 16; s <<= 1) {
#pragma unroll
            for (int q = 0; q < 4; q++)
                tm[q] = fmaxf(tm[q], __shfl_xor_sync(0xFFFFFFFFu, tm[q], s));
        }

        float f[4], ls[4];
#pragma unroll
        for (int q = 0; q < 4; q++) {
            float Mn = fmaxf(Mrun[q], tm[q]);
            f[q] = fexp(Mrun[q] - Mn);
            Mrun[q] = Mn;
            ls[q] = 0.f;
        }

#pragma unroll
        for (int j = 0; j < 4; j++) {
            bool ok = (m0 + tx * 4 + j) < Mi;
#pragma unroll
            for (int q = 0; q < 4; q++) {
                float p = ok ? fexp(S[q][j] - Mrun[q]) : 0.f;
                S[q][j] = p;
                ls[q] += p;
            }
        }
#pragma unroll
        for (int s = 1; s < 16; s <<= 1) {
#pragma unroll
            for (int q = 0; q < 4; q++)
                ls[q] += __shfl_xor_sync(0xFFFFFFFFu, ls[q], s);
        }
#pragma unroll
        for (int q = 0; q < 4; q++)
            Srun[q] = fmaf(Srun[q], f[q], ls[q]);

        ull f01 = pack2(f[0], f[1]);
        ull f23 = pack2(f[2], f[3]);
#pragma unroll
        for (int j = 0; j < 4; j++) { fmul2(acco[0][j], f01); fmul2(acco[1][j], f23); }

#pragma unroll
        for (int j = 0; j < 4; j++) {
            float4 v = {S[0][j], S[1][j], S[2][j], S[3][j]};
            *(float4*)&Pt[tx * 4 + j][ty * 4] = v;
        }
        __syncthreads();

#pragma unroll 16
        for (int mm = 0; mm < 64; mm++) {
            float4 a = *(const float4*)&Pt[mm][ty * 4];
            const ull* a2 = (const ull*)&a;
            float4 bv = *(const float4*)&Gs[mm][tx * 4];
            const float* bf = (const float*)&bv;
#pragma unroll
            for (int j = 0; j < 4; j++) {
                ull bd = dup2(bf[j]);
                ffma2(acco[0][j], a2[0], bd);
                ffma2(acco[1][j], a2[1], bd);
            }
        }
        __syncthreads();
    }

    float inv[4];
#pragma unroll
    for (int q = 0; q < 4; q++) inv[q] = 1.0f / Srun[q];
#pragma unroll
    for (int q = 0; q < 4; q++) {
        float4 v;
        float* vv = (float*)&v;
#pragma unroll
        for (int j = 0; j < 4; j++) {
            float2 w = *(float2*)&acco[q >> 1][j];
            vv[j] = ((q & 1) ? w.y : w.x) * inv[q];
        }
        *(float4*)(Ob + ((long)n0 + ty * 4 + q) * PLc + tx * 4) = v;
    }
}

// ---------------------------------------------------------------------------
// Tiled SGEMM (FFMA2, double-buffered). STAT: per-row sum/sumsq atomics into
// statOut + (batch / statDiv)*2*CPc  (per-scale regions for the batched Z).
// ---------------------------------------------------------------------------
template<int BM, int BN, int TM, int TN, bool TAR, bool TBR, bool STAT, bool ATOM>
__global__ void __launch_bounds__(256) gemm_k(
    const float* __restrict__ A, const float* __restrict__ B, float* __restrict__ C,
    int M, int N, int K, int lda, int ldb, int ldc,
    long sA, long sB, long sC, int ksplit, int kchunk,
    float* __restrict__ statOut, int statDiv)
{
    constexpr int BK = 16;
    constexpr int LA = BM * BK / 1024;
    constexpr int LB = BN * BK / 1024;
    constexpr int MV = BM / 4, NV = BN / 4;
    constexpr int TX = BN / TN;
    static_assert((BM / TM) * (BN / TN) == 256, "256 threads");
    static_assert(TM % 2 == 0, "TM even");

    __shared__ float As[2][BK][BM];
    __shared__ float Bs[2][BK][BN + (TBR ? 1 : 0)];

    const int b  = blockIdx.z / ksplit;
    const int kz = blockIdx.z - b * ksplit;
    A += (long)b * sA;  B += (long)b * sB;  C += (long)b * sC;

    const int kbeg = kz * kchunk;
    const int kend = min(K, kbeg + kchunk);
    const int m0 = blockIdx.y * BM, n0 = blockIdx.x * BN;
    const int tid = threadIdx.x;
    const int ty = tid / TX, tx = tid - ty * TX;

    float4 ra[LA], rb[LB];

    auto fetchA = [&](int k0) {
#pragma unroll
        for (int r = 0; r < LA; r++) {
            int e = tid + r * 256;
            float4 v = {0.f, 0.f, 0.f, 0.f};
            if (!TAR) {
                int k = e / MV, mq = e - k * MV;
                int gm = m0 + mq * 4;
                if (k0 + k < kend && gm + 3 < M)
                    v = *(const float4*)(A + (long)(k0 + k) * lda + gm);
            } else {
                int m = e / 4, kq = e - m * 4;
                int gm = m0 + m, gk = k0 + kq * 4;
                if (gm < M) {
                    if (gk + 3 < kend) {
                        v = *(const float4*)(A + (long)gm * lda + gk);
                    } else {
                        float* vv = (float*)&v;
#pragma unroll
                        for (int q = 0; q < 4; q++)
                            if (gk + q < kend) vv[q] = A[(long)gm * lda + gk + q];
                    }
                }
            }
            ra[r] = v;
        }
    };
    auto storeA = [&](int buf) {
#pragma unroll
        for (int r = 0; r < LA; r++) {
            int e = tid + r * 256;
            if (!TAR) {
                int k = e / MV, mq = e - k * MV;
                *(float4*)&As[buf][k][mq * 4] = ra[r];
            } else {
                int m = e / 4, kq = e - m * 4;
                As[buf][kq * 4 + 0][m] = ra[r].x; As[buf][kq * 4 + 1][m] = ra[r].y;
                As[buf][kq * 4 + 2][m] = ra[r].z; As[buf][kq * 4 + 3][m] = ra[r].w;
            }
        }
    };
    auto fetchB = [&](int k0) {
#pragma unroll
        for (int r = 0; r < LB; r++) {
            int e = tid + r * 256;
            float4 v = {0.f, 0.f, 0.f, 0.f};
            if (!TBR) {
                int k = e / NV, nq = e - k * NV;
                int gn = n0 + nq * 4;
                if (k0 + k < kend && gn + 3 < N)
                    v = *(const float4*)(B + (long)(k0 + k) * ldb + gn);
            } else {
                int n = e / 4, kq = e - n * 4;
                int gn = n0 + n, gk = k0 + kq * 4;
                if (gn < N) {
                    if (gk + 3 < kend) {
                        v = *(const float4*)(B + (long)gn * ldb + gk);
                    } else {
                        float* vv = (float*)&v;
#pragma unroll
                        for (int q = 0; q < 4; q++)
                            if (gk + q < kend) vv[q] = B[(long)gn * ldb + gk + q];
                    }
                }
            }
            rb[r] = v;
        }
    };
    auto storeB = [&](int buf) {
#pragma unroll
        for (int r = 0; r < LB; r++) {
            int e = tid + r * 256;
            if (!TBR) {
                int k = e / NV, nq = e - k * NV;
                *(float4*)&Bs[buf][k][nq * 4] = rb[r];
            } else {
                int n = e / 4, kq = e - n * 4;
                Bs[buf][kq * 4 + 0][n] = rb[r].x; Bs[buf][kq * 4 + 1][n] = rb[r].y;
                Bs[buf][kq * 4 + 2][n] = rb[r].z; Bs[buf][kq * 4 + 3][n] = rb[r].w;
            }
        }
    };

    ull acc2[TM / 2][TN];
#pragma unroll
    for (int i = 0; i < TM / 2; i++)
#pragma unroll
        for (int j = 0; j < TN; j++) acc2[i][j] = 0ULL;

    const int nkt = (kend - kbeg + BK - 1) / BK;

    fetchA(kbeg); fetchB(kbeg);
    storeA(0); storeB(0);
    __syncthreads();

    for (int t = 0; t < nkt; t++) {
        const int cur = t & 1, nxt = cur ^ 1;
        const bool more = (t + 1) < nkt;
        if (more) { fetchA(kbeg + (t + 1) * BK); fetchB(kbeg + (t + 1) * BK); }

#pragma unroll
        for (int kk = 0; kk < BK; kk++) {
            float4 av[TM / 4];
#pragma unroll
            for (int i = 0; i < TM / 4; i++)
                av[i] = *(const float4*)&As[cur][kk][ty * TM + i * 4];
            const ull* a2 = (const ull*)av;

            ull b2[TN];
            if (!TBR) {
                float4 bv[TN / 4];
#pragma unroll
                for (int j = 0; j < TN / 4; j++)
                    bv[j] = *(const float4*)&Bs[cur][kk][tx * TN + j * 4];
                const float* bf = (const float*)bv;
#pragma unroll
                for (int j = 0; j < TN; j++) b2[j] = dup2(bf[j]);
            } else {
#pragma unroll
                for (int j = 0; j < TN; j++) b2[j] = dup2(Bs[cur][kk][tx * TN + j]);
            }

#pragma unroll
            for (int i = 0; i < TM / 2; i++)
#pragma unroll
                for (int j = 0; j < TN; j++)
                    ffma2(acc2[i][j], a2[i], b2[j]);
        }

        if (more) { storeA(nxt); storeB(nxt); }
        __syncthreads();
    }

#pragma unroll
    for (int i2 = 0; i2 < TM / 2; i2++) {
        int gmA = m0 + ty * TM + 2 * i2;
        int gmB = gmA + 1;
#pragma unroll
        for (int j = 0; j < TN; j++) {
            int gn = n0 + tx * TN + j;
            if (gn >= N) continue;
            float2 w = *(float2*)&acc2[i2][j];
            if (gmA < M) {
                if (ATOM) atomicAdd(&C[(long)gmA * ldc + gn], w.x);
                else      C[(long)gmA * ldc + gn] = w.x;
            }
            if (gmB < M) {
                if (ATOM) atomicAdd(&C[(long)gmB * ldc + gn], w.y);
                else      C[(long)gmB * ldc + gn] = w.y;
            }
        }
    }

    if (STAT) {
        float* sBase = statOut + (long)(b / statDiv) * (2 * CPc);
        float* red = &As[0][0][0];
        if (tid < 2 * BM) red[tid] = 0.f;
        __syncthreads();
#pragma unroll
        for (int i2 = 0; i2 < TM / 2; i2++) {
            float sX = 0.f, s2X = 0.f, sY = 0.f, s2Y = 0.f;
#pragma unroll
            for (int j = 0; j < TN; j++) {
                float2 w = *(float2*)&acc2[i2][j];
                sX += w.x; s2X = fmaf(w.x, w.x, s2X);
                sY += w.y; s2Y = fmaf(w.y, w.y, s2Y);
            }
            atomicAdd(&red[ty * TM + 2 * i2],          sX);
            atomicAdd(&red[BM + ty * TM + 2 * i2],     s2X);
            atomicAdd(&red[ty * TM + 2 * i2 + 1],      sY);
            atomicAdd(&red[BM + ty * TM + 2 * i2 + 1], s2Y);
        }
        __syncthreads();
        if (tid < BM && m0 + tid < M) {
            atomicAdd(&sBase[m0 + tid], red[tid]);
            atomicAdd(&sBase[CPc + m0 + tid], red[BM + tid]);
        }
    }
}

// ---------------------------------------------------------------------------
// BN finalize (all 5 scales) + fused apply-sum over all 5 scales
// ---------------------------------------------------------------------------
__global__ void bn_finalize_k(const float* __restrict__ stat,
                              float* __restrict__ mean, float* __restrict__ istd)
{
    int s = blockIdx.x, c = threadIdx.x;
    const float inv = 1.0f / (float)(NB * NQc);
    float m = stat[s * 2 * CPc + c] * inv;
    float v = stat[s * 2 * CPc + CPc + c] * inv - m * m;
    mean[s * CPc + c] = m;
    istd[s * CPc + c] = rsqrtf(v + 1e-5f);
}

__global__ void bn_apply_all_k(const float* __restrict__ Z,
    const float* __restrict__ mean, const float* __restrict__ istd,
    const float* __restrict__ gm0, const float* __restrict__ bt0,
    const float* __restrict__ gm1, const float* __restrict__ bt1,
    const float* __restrict__ gm2, const float* __restrict__ bt2,
    const float* __restrict__ gm3, const float* __restrict__ bt3,
    const float* __restrict__ gm4, const float* __restrict__ bt4,
    float* __restrict__ out)
{
    const float* G[5] = {gm0, gm1, gm2, gm3, gm4};
    const float* Bt[5] = {bt0, bt1, bt2, bt3, bt4};
    long i = ((long)blockIdx.x * 256 + threadIdx.x) * 4;
    int c = (int)((i / NQc) % CPc);
    float4 o = {0.f, 0.f, 0.f, 0.f};
#pragma unroll
    for (int s = 0; s < 5; s++) {
        float a = istd[s * CPc + c] * G[s][c];
        float bb = fmaf(-mean[s * CPc + c], a, Bt[s][c]);
        float4 z = *(const float4*)(Z + (long)s * ZSZ + i);
        o.x = fmaf(z.x, a, o.x + bb);
        o.y = fmaf(z.y, a, o.y + bb);
        o.z = fmaf(z.z, a, o.z + bb);
        o.w = fmaf(z.w, a, o.w + bb);
    }
    *(float4*)(out + i) = o;
}

// ---------------------------------------------------------------------------
// Host launch
// ---------------------------------------------------------------------------
extern "C" void kernel_launch(void* const* d_in, const int* in_sizes, int n_in,
                              void* d_out, int out_size)
{
    (void)in_sizes; (void)n_in; (void)out_size;

    const float* persp = (const float*)d_in[0];
    const float* resp[5] = {
        (const float*)d_in[1], (const float*)d_in[2], (const float*)d_in[3],
        (const float*)d_in[4], (const float*)d_in[5] };
    const float* t_w = (const float*)d_in[6];
    const float* z_w = (const float*)d_in[7];
    float* out = (float*)d_out;

    static const int MsH[5]    = {2304, 2304, 576, 144, 36};
    static const long PGoffH[5] = {0L,
        (long)NB * 128 * 2304,
        (long)NB * 128 * (2304 + 2304),
        (long)NB * 128 * (2304 + 2304 + 576),
        (long)NB * 128 * (2304 + 2304 + 576 + 144)};
    static const long PGWoffH[5] = {0L, 128L * 64, 128L * 320, 128L * 832, 128L * 1856};

    float *T, *PGw, *PG, *O, *Z, *stat, *mean, *istd;
    cudaGetSymbolAddress((void**)&T,    g_T);
    cudaGetSymbolAddress((void**)&PGw,  g_PGw);
    cudaGetSymbolAddress((void**)&PG,   g_PG);
    cudaGetSymbolAddress((void**)&O,    g_O);
    cudaGetSymbolAddress((void**)&Z,    g_Z);
    cudaGetSymbolAddress((void**)&stat, g_stat);
    cudaGetSymbolAddress((void**)&mean, g_mean);
    cudaGetSymbolAddress((void**)&istd, g_istd);

    const int FLASH_SMEM = 16896 * 4;
    cudaFuncSetAttribute(flash_k,
        cudaFuncAttributeMaxDynamicSharedMemorySize, FLASH_SMEM);

    // ---- T = t_w[64,256] @ persp ----
    gemm_k<64, 128, 4, 8, true, false, false, false>
        <<<dim3(NQc / 128, 1, NB), 256>>>(
            t_w, persp, T, PLc, NQc, CPc, CPc, NQc, NQc,
            0L, (long)CPc * NQc, (long)PLc * NQc, 1, CPc, nullptr, 1);

    // ---- stage weights + PG projections for all scales ----
    cudaMemsetAsync(PG, 0, PG_TOTAL * 4, 0);
    for (int i = 0; i < 5; i++) {
        const int Cr = CRs[i];
        const int Mi = MsH[i];
        const float* p_w  = (const float*)d_in[8 + 4 * i];
        const float* g_wt = (const float*)d_in[9 + 4 * i];
        float* Wd = PGw + PGWoffH[i];
        cudaMemcpyAsync(Wd,            p_w, (size_t)PLc * Cr * 4,
                        cudaMemcpyDeviceToDevice, 0);
        cudaMemcpyAsync(Wd + PLc * Cr, g_wt, (size_t)PLc * Cr * 4,
                        cudaMemcpyDeviceToDevice, 0);

        float* Cd = PG + PGoffH[i];
        int ks = Cr >= 128 ? Cr / 128 : 1;
        int kchunk = Cr / ks;
        if (Mi >= 128) {
            dim3 grid((Mi + 127) / 128, 1, NB * ks);
            if (ks > 1)
                gemm_k<128, 128, 8, 8, true, false, false, true>
                    <<<grid, 256>>>(Wd, resp[i], Cd, 128, Mi, Cr, Cr, Mi, Mi,
                                    0L, (long)Cr * Mi, (long)128 * Mi, ks, kchunk,
                                    nullptr, 1);
            else
                gemm_k<128, 128, 8, 8, true, false, false, false>
                    <<<grid, 256>>>(Wd, resp[i], Cd, 128, Mi, Cr, Cr, Mi, Mi,
                                    0L, (long)Cr * Mi, (long)128 * Mi, 1, Cr,
                                    nullptr, 1);
        } else {
            dim3 grid((Mi + 63) / 64, 1, NB * ks);
            gemm_k<128, 64, 8, 4, true, false, false, true>
                <<<grid, 256>>>(Wd, resp[i], Cd, 128, Mi, Cr, Cr, Mi, Mi,
                                0L, (long)Cr * Mi, (long)128 * Mi, ks, kchunk,
                                nullptr, 1);
        }
    }

    // ---- merged flash attention over all 5 scales ----
    flash_k<<<dim3(NQc / 64, 5 * NB), 256, FLASH_SMEM>>>(T, PG, O);

    // ---- batched Z-GEMM (5*NB batches) with per-scale BN stats ----
    cudaMemsetAsync(stat, 0, (size_t)5 * 2 * CPc * 4, 0);
    {
        dim3 grid(NQc / 128, CPc / 64, 5 * NB);
        gemm_k<64, 128, 4, 8, true, false, true, false>
            <<<grid, 256>>>(z_w, O, Z, CPc, NQc, PLc, PLc, NQc, NQc,
                            0L, (long)NQc * PLc, (long)CPc * NQc, 1, PLc,
                            stat, NB);
    }

    bn_finalize_k<<<5, 256>>>(stat, mean, istd);

    {
        long total4 = (long)NB * CPc * NQc / 4;
        bn_apply_all_k<<<(unsigned)(total4 / 256), 256>>>(
            Z, mean, istd,
            (const float*)d_in[10], (const float*)d_in[11],
            (const float*)d_in[14], (const float*)d_in[15],
            (const float*)d_in[18], (const float*)d_in[19],
            (const float*)d_in[22], (const float*)d_in[23],
            (const float*)d_in[26], (const float*)d_in[27],
            out);
    }
}

// round 9
// speedup vs baseline: 1.4874x; 1.1421x over previous
#include <cuda_runtime.h>
#include <math.h>

#define NB   4
#define CPc  256
#define PLc  64
#define NQc  2304

typedef unsigned long long ull;

// per-scale M sizes and PG offsets (floats), compile-time
__constant__ int  d_Mi[5]    = {2304, 2304, 576, 144, 36};
__constant__ long d_PGoff[5] = {0L,
                                (long)NB * 128 * 2304,
                                (long)NB * 128 * (2304 + 2304),
                                (long)NB * 128 * (2304 + 2304 + 576),
                                (long)NB * 128 * (2304 + 2304 + 576 + 144)};
#define PG_TOTAL ((long)NB * 128 * (2304 + 2304 + 576 + 144 + 36))
#define OSZ ((long)NB * NQc * PLc)
#define ZSZ ((long)NB * CPc * NQc)

// ---------------------------------------------------------------------------
// Scratch
// ---------------------------------------------------------------------------
__device__ float g_T  [NB * PLc * NQc];
__device__ float g_PG [NB * 128 * (2304 + 2304 + 576 + 144 + 36)];
__device__ float g_O  [5 * NB * NQc * PLc];
__device__ float g_Z  [5 * NB * CPc * NQc];
__device__ float g_stat[5 * 2 * CPc];
__device__ float g_mean[5 * CPc];
__device__ float g_istd[5 * CPc];

// ---------------------------------------------------------------------------
// Helpers
// ---------------------------------------------------------------------------
__device__ __forceinline__ float fexp(float x)
{
    x = fmaxf(x, -87.0f);
    const float L2E = 1.4426950408889634f;
    float t = fmaf(x, L2E, 12582912.0f);
    float n = t - 12582912.0f;
    float f = fmaf(x, L2E, -n);
    float p = 1.33335581e-3f;
    p = fmaf(p, f, 9.61812911e-3f);
    p = fmaf(p, f, 5.55041087e-2f);
    p = fmaf(p, f, 2.40226507e-1f);
    p = fmaf(p, f, 6.93147180e-1f);
    p = fmaf(p, f, 1.0f);
    int ni = (int)n;
    ni = max(-126, min(127, ni));
    return p * __int_as_float((ni + 127) << 23);
}

__device__ __forceinline__ void ffma2(ull& c, ull a, ull b)
{
    asm("fma.rn.f32x2 %0, %1, %2, %0;" : "+l"(c) : "l"(a), "l"(b));
}
__device__ __forceinline__ void fmul2(ull& c, ull b)
{
    asm("mul.rn.f32x2 %0, %0, %1;" : "+l"(c) : "l"(b));
}
__device__ __forceinline__ ull dup2(float x)
{
    ull r;
    unsigned u = __float_as_uint(x);
    asm("mov.b64 %0, {%1, %1};" : "=l"(r) : "r"(u));
    return r;
}
__device__ __forceinline__ ull pack2(float lo, float hi)
{
    ull r;
    asm("mov.b64 %0, {%1, %2};" : "=l"(r) : "f"(lo), "f"(hi));
    return r;
}

// ===========================================================================
// Unified projection launch: 11 segments (T, P0,G0, P1,G1, ... P4,G4),
// each  C[64,N] (+=)  W[64,K] @ X[K,N]  batched over b, split-K via atomics.
// One 1760-block launch replaces 6 GEMM launches + 10 memcpys.
// ===========================================================================
struct ProjArgs {
    const float* W[11];
    const float* X[11];
    float*       C[11];
};

__constant__ int  c_segN  [11] = {2304, 2304,2304, 2304,2304, 576,576, 144,144, 36,36};
__constant__ int  c_segK  [11] = {256, 64,64, 256,256, 512,512, 1024,1024, 2048,2048};
__constant__ int  c_segKs [11] = {2, 1,1, 2,2, 4,4, 8,8, 16,16};
__constant__ int  c_segKch[11] = {128, 64,64, 128,128, 128,128, 128,128, 128,128};
__constant__ int  c_segNt [11] = {36, 36,36, 36,36, 9,9, 3,3, 1,1};
__constant__ int  c_segStart[12] = {0,288,432,576,864,1152,1296,1440,1536,1632,1696,1760};
__constant__ long c_segSX [11] = {256L*2304, 64L*2304,64L*2304, 256L*2304,256L*2304,
                                  512L*576,512L*576, 1024L*144,1024L*144, 2048L*36,2048L*36};
__constant__ long c_segSC [11] = {64L*2304, 128L*2304,128L*2304, 128L*2304,128L*2304,
                                  128L*576,128L*576, 128L*144,128L*144, 128L*36,128L*36};

__global__ void __launch_bounds__(256) proj_k(ProjArgs pa)
{
    __shared__ float As[2][16][64];
    __shared__ float Bs[2][16][64];

    const int bid = blockIdx.x;
    int seg = 0;
#pragma unroll
    for (int s = 1; s < 11; s++) if (bid >= c_segStart[s]) seg = s;
    const int local = bid - c_segStart[seg];
    const int ntl = c_segNt[seg];
    const int nt = local % ntl;
    const int rest = local / ntl;
    const int ks = c_segKs[seg];
    const int kz = rest % ks;
    const int b  = rest / ks;

    const int N = c_segN[seg];
    const int K = c_segK[seg];
    const int kchunk = c_segKch[seg];
    const int kbeg = kz * kchunk;
    const int kend = min(K, kbeg + kchunk);
    const int n0 = nt * 64;

    const float* A  = pa.W[seg];                          // [64, K] row-major
    const float* Bx = pa.X[seg] + (long)b * c_segSX[seg]; // [K, N] K-major
    float*       C  = pa.C[seg] + (long)b * c_segSC[seg]; // [64, N]

    const int tid = threadIdx.x;
    const int ty = tid >> 4, tx = tid & 15;

    float4 ra, rb;
    const int am = tid >> 2, akq = (tid & 3) * 4;         // A: 64m x 16k
    const int bk = tid >> 4, bnq = (tid & 15) * 4;        // B: 16k x 64n
    const int bgn = n0 + bnq;

    auto fetchA = [&](int k0) {
        ra = *(const float4*)(A + (long)am * K + k0 + akq);
    };
    auto storeA = [&](int buf) {
        As[buf][akq + 0][am] = ra.x; As[buf][akq + 1][am] = ra.y;
        As[buf][akq + 2][am] = ra.z; As[buf][akq + 3][am] = ra.w;
    };
    auto fetchB = [&](int k0) {
        rb = make_float4(0.f, 0.f, 0.f, 0.f);
        if (bgn + 3 < N) rb = *(const float4*)(Bx + (long)(k0 + bk) * N + bgn);
    };
    auto storeB = [&](int buf) {
        *(float4*)&Bs[buf][bk][bnq] = rb;
    };

    ull acc2[2][4];
#pragma unroll
    for (int i = 0; i < 2; i++)
#pragma unroll
        for (int j = 0; j < 4; j++) acc2[i][j] = 0ULL;

    const int nkt = (kend - kbeg) / 16;

    fetchA(kbeg); fetchB(kbeg);
    storeA(0); storeB(0);
    __syncthreads();

    for (int t = 0; t < nkt; t++) {
        const int cur = t & 1, nxt = cur ^ 1;
        const bool more = (t + 1) < nkt;
        if (more) { fetchA(kbeg + (t + 1) * 16); fetchB(kbeg + (t + 1) * 16); }

#pragma unroll
        for (int kk = 0; kk < 16; kk++) {
            float4 a = *(const float4*)&As[cur][kk][ty * 4];
            const ull* a2 = (const ull*)&a;
            float4 bv = *(const float4*)&Bs[cur][kk][tx * 4];
            const float* bf = (const float*)&bv;
#pragma unroll
            for (int j = 0; j < 4; j++) {
                ull bd = dup2(bf[j]);
                ffma2(acc2[0][j], a2[0], bd);
                ffma2(acc2[1][j], a2[1], bd);
            }
        }

        if (more) { storeA(nxt); storeB(nxt); }
        __syncthreads();
    }

#pragma unroll
    for (int i2 = 0; i2 < 2; i2++) {
        int gmA = ty * 4 + 2 * i2;
#pragma unroll
        for (int j = 0; j < 4; j++) {
            int gn = n0 + tx * 4 + j;
            if (gn >= N) continue;
            float2 w = *(float2*)&acc2[i2][j];
            if (ks > 1) {
                atomicAdd(&C[(long)gmA * N + gn], w.x);
                atomicAdd(&C[(long)(gmA + 1) * N + gn], w.y);
            } else {
                C[(long)gmA * N + gn] = w.x;
                C[(long)(gmA + 1) * N + gn] = w.y;
            }
        }
    }
}

// ---------------------------------------------------------------------------
// Merged flash attention over ALL scales: blockIdx.y = scale*NB + b.
// ---------------------------------------------------------------------------
__global__ void __launch_bounds__(256) flash_k(
    const float* __restrict__ T, const float* __restrict__ PG,
    float* __restrict__ O)
{
    extern __shared__ float sm[];
    float (*Tq)[64] = (float(*)[64])(sm);
    float (*Ps)[64] = (float(*)[64])(sm + 4096);
    float (*Gs)[68] = (float(*)[68])(sm + 8192);
    float (*Pt)[68] = (float(*)[68])(sm + 12544);

    const int sc = blockIdx.y >> 2;
    const int b  = blockIdx.y & 3;
    const int Mi = d_Mi[sc];
    const int n0 = blockIdx.x * 64;
    const int tid = threadIdx.x;
    const int ty = tid >> 4, tx = tid & 15;

    const float* Tb = T + (long)b * PLc * NQc;
    const float* Pb = PG + d_PGoff[sc] + (long)b * 2 * PLc * Mi;
    const float* Gb = Pb + (long)PLc * Mi;
    float* Ob = O + (long)sc * OSZ + (long)b * NQc * PLc;

#pragma unroll
    for (int r = 0; r < 4; r++) {
        int e = (tid + r * 256) * 4;
        int k = e >> 6, q = e & 63;
        *(float4*)&Tq[k][q] = *(const float4*)(Tb + (long)k * NQc + n0 + q);
    }

    float Mrun[4], Srun[4];
#pragma unroll
    for (int q = 0; q < 4; q++) { Mrun[q] = -1e30f; Srun[q] = 0.f; }
    ull acco[2][4];
#pragma unroll
    for (int i = 0; i < 2; i++)
#pragma unroll
        for (int j = 0; j < 4; j++) acco[i][j] = 0ULL;

    for (int m0 = 0; m0 < Mi; m0 += 64) {
#pragma unroll
        for (int r = 0; r < 4; r++) {
            int e = (tid + r * 256) * 4;
            int k = e >> 6, mm = e & 63;
            float4 v = {0.f, 0.f, 0.f, 0.f};
            if (m0 + mm < Mi) v = *(const float4*)(Pb + (long)k * Mi + m0 + mm);
            *(float4*)&Ps[k][mm] = v;
        }
#pragma unroll
        for (int r = 0; r < 4; r++) {
            int e = tid + r * 256;
            int c = e >> 4, mq = (e & 15) * 4;
            float4 v = {0.f, 0.f, 0.f, 0.f};
            if (m0 + mq < Mi) v = *(const float4*)(Gb + (long)c * Mi + m0 + mq);
            Gs[mq + 0][c] = v.x; Gs[mq + 1][c] = v.y;
            Gs[mq + 2][c] = v.z; Gs[mq + 3][c] = v.w;
        }
        __syncthreads();

        ull accs[2][4];
#pragma unroll
        for (int i = 0; i < 2; i++)
#pragma unroll
            for (int j = 0; j < 4; j++) accs[i][j] = 0ULL;

#pragma unroll 16
        for (int kk = 0; kk < 64; kk++) {
            float4 a = *(const float4*)&Tq[kk][ty * 4];
            const ull* a2 = (const ull*)&a;
            float4 bv = *(const float4*)&Ps[kk][tx * 4];
            const float* bf = (const float*)&bv;
#pragma unroll
            for (int j = 0; j < 4; j++) {
                ull bd = dup2(bf[j]);
                ffma2(accs[0][j], a2[0], bd);
                ffma2(accs[1][j], a2[1], bd);
            }
        }

        float S[4][4];
#pragma unroll
        for (int qp = 0; qp < 2; qp++)
#pragma unroll
            for (int j = 0; j < 4; j++) {
                float2 w = *(float2*)&accs[qp][j];
                S[2 * qp][j] = w.x;
                S[2 * qp + 1][j] = w.y;
            }

        float tm[4];
#pragma unroll
        for (int q = 0; q < 4; q++)
            tm[q] = fmaxf(fmaxf(S[q][0], S[q][1]), fmaxf(S[q][2], S[q][3]));
#pragma unroll
        for (int s = 1; s < 16; s <<= 1) {
#pragma unroll
            for (int q = 0; q < 4; q++)
                tm[q] = fmaxf(tm[q], __shfl_xor_sync(0xFFFFFFFFu, tm[q], s));
        }

        float f[4], ls[4];
#pragma unroll
        for (int q = 0; q < 4; q++) {
            float Mn = fmaxf(Mrun[q], tm[q]);
            f[q] = fexp(Mrun[q] - Mn);
            Mrun[q] = Mn;
            ls[q] = 0.f;
        }

#pragma unroll
        for (int j = 0; j < 4; j++) {
            bool ok = (m0 + tx * 4 + j) < Mi;
#pragma unroll
            for (int q = 0; q < 4; q++) {
                float p = ok ? fexp(S[q][j] - Mrun[q]) : 0.f;
                S[q][j] = p;
                ls[q] += p;
            }
        }
#pragma unroll
        for (int s = 1; s < 16; s <<= 1) {
#pragma unroll
            for (int q = 0; q < 4; q++)
                ls[q] += __shfl_xor_sync(0xFFFFFFFFu, ls[q], s);
        }
#pragma unroll
        for (int q = 0; q < 4; q++)
            Srun[q] = fmaf(Srun[q], f[q], ls[q]);

        ull f01 = pack2(f[0], f[1]);
        ull f23 = pack2(f[2], f[3]);
#pragma unroll
        for (int j = 0; j < 4; j++) { fmul2(acco[0][j], f01); fmul2(acco[1][j], f23); }

#pragma unroll
        for (int j = 0; j < 4; j++) {
            float4 v = {S[0][j], S[1][j], S[2][j], S[3][j]};
            *(float4*)&Pt[tx * 4 + j][ty * 4] = v;
        }
        __syncthreads();

#pragma unroll 16
        for (int mm = 0; mm < 64; mm++) {
            float4 a = *(const float4*)&Pt[mm][ty * 4];
            const ull* a2 = (const ull*)&a;
            float4 bv = *(const float4*)&Gs[mm][tx * 4];
            const float* bf = (const float*)&bv;
#pragma unroll
            for (int j = 0; j < 4; j++) {
                ull bd = dup2(bf[j]);
                ffma2(acco[0][j], a2[0], bd);
                ffma2(acco[1][j], a2[1], bd);
            }
        }
        __syncthreads();
    }

    float inv[4];
#pragma unroll
    for (int q = 0; q < 4; q++) inv[q] = 1.0f / Srun[q];
#pragma unroll
    for (int q = 0; q < 4; q++) {
        float4 v;
        float* vv = (float*)&v;
#pragma unroll
        for (int j = 0; j < 4; j++) {
            float2 w = *(float2*)&acco[q >> 1][j];
            vv[j] = ((q & 1) ? w.y : w.x) * inv[q];
        }
        *(float4*)(Ob + ((long)n0 + ty * 4 + q) * PLc + tx * 4) = v;
    }
}

// ---------------------------------------------------------------------------
// Batched Z-GEMM (FFMA2, double-buffered) with fused per-scale BN partials.
// ---------------------------------------------------------------------------
template<int BM, int BN, int TM, int TN>
__global__ void __launch_bounds__(256) zgemm_k(
    const float* __restrict__ A, const float* __restrict__ B, float* __restrict__ C,
    int M, int N, int K, int lda, int ldb, int ldc,
    long sB, long sC, float* __restrict__ statOut, int statDiv)
{
    constexpr int BK = 16;
    constexpr int LA = BM * BK / 1024;
    constexpr int LB = BN * BK / 1024;
    constexpr int NV = BN / 4;
    constexpr int TX = BN / TN;
    static_assert((BM / TM) * (BN / TN) == 256, "256 threads");

    __shared__ float As[2][BK][BM];
    __shared__ float Bs[2][BK][BN];

    const int b = blockIdx.z;
    B += (long)b * sB;  C += (long)b * sC;

    const int m0 = blockIdx.y * BM, n0 = blockIdx.x * BN;
    const int tid = threadIdx.x;
    const int ty = tid / TX, tx = tid - ty * TX;

    float4 ra[LA], rb[LB];

    auto fetchA = [&](int k0) {      // A row-major [M,K]
#pragma unroll
        for (int r = 0; r < LA; r++) {
            int e = tid + r * 256;
            int m = e / 4, kq = e - m * 4;
            ra[r] = *(const float4*)(A + (long)(m0 + m) * lda + k0 + kq * 4);
        }
    };
    auto storeA = [&](int buf) {
#pragma unroll
        for (int r = 0; r < LA; r++) {
            int e = tid + r * 256;
            int m = e / 4, kq = e - m * 4;
            As[buf][kq * 4 + 0][m] = ra[r].x; As[buf][kq * 4 + 1][m] = ra[r].y;
            As[buf][kq * 4 + 2][m] = ra[r].z; As[buf][kq * 4 + 3][m] = ra[r].w;
        }
    };
    auto fetchB = [&](int k0) {      // B K-major [K,N]
#pragma unroll
        for (int r = 0; r < LB; r++) {
            int e = tid + r * 256;
            int k = e / NV, nq = e - k * NV;
            rb[r] = *(const float4*)(B + (long)(k0 + k) * ldb + n0 + nq * 4);
        }
    };
    auto storeB = [&](int buf) {
#pragma unroll
        for (int r = 0; r < LB; r++) {
            int e = tid + r * 256;
            int k = e / NV, nq = e - k * NV;
            *(float4*)&Bs[buf][k][nq * 4] = rb[r];
        }
    };

    ull acc2[TM / 2][TN];
#pragma unroll
    for (int i = 0; i < TM / 2; i++)
#pragma unroll
        for (int j = 0; j < TN; j++) acc2[i][j] = 0ULL;

    const int nkt = K / BK;

    fetchA(0); fetchB(0);
    storeA(0); storeB(0);
    __syncthreads();

    for (int t = 0; t < nkt; t++) {
        const int cur = t & 1, nxt = cur ^ 1;
        const bool more = (t + 1) < nkt;
        if (more) { fetchA((t + 1) * BK); fetchB((t + 1) * BK); }

#pragma unroll
        for (int kk = 0; kk < BK; kk++) {
            float4 av[TM / 4];
#pragma unroll
            for (int i = 0; i < TM / 4; i++)
                av[i] = *(const float4*)&As[cur][kk][ty * TM + i * 4];
            const ull* a2 = (const ull*)av;

            float4 bv[TN / 4];
#pragma unroll
            for (int j = 0; j < TN / 4; j++)
                bv[j] = *(const float4*)&Bs[cur][kk][tx * TN + j * 4];
            const float* bf = (const float*)bv;

#pragma unroll
            for (int j = 0; j < TN; j++) {
                ull bd = dup2(bf[j]);
#pragma unroll
                for (int i = 0; i < TM / 2; i++)
                    ffma2(acc2[i][j], a2[i], bd);
            }
        }

        if (more) { storeA(nxt); storeB(nxt); }
        __syncthreads();
    }

#pragma unroll
    for (int i2 = 0; i2 < TM / 2; i2++) {
        int gmA = m0 + ty * TM + 2 * i2;
#pragma unroll
        for (int j = 0; j < TN; j++) {
            int gn = n0 + tx * TN + j;
            float2 w = *(float2*)&acc2[i2][j];
            C[(long)gmA * ldc + gn] = w.x;
            C[(long)(gmA + 1) * ldc + gn] = w.y;
        }
    }

    // fused BN partials
    {
        float* sBase = statOut + (long)(b / statDiv) * (2 * CPc);
        float* red = &As[0][0][0];
        if (tid < 2 * BM) red[tid] = 0.f;
        __syncthreads();
#pragma unroll
        for (int i2 = 0; i2 < TM / 2; i2++) {
            float sX = 0.f, s2X = 0.f, sY = 0.f, s2Y = 0.f;
#pragma unroll
            for (int j = 0; j < TN; j++) {
                float2 w = *(float2*)&acc2[i2][j];
                sX += w.x; s2X = fmaf(w.x, w.x, s2X);
                sY += w.y; s2Y = fmaf(w.y, w.y, s2Y);
            }
            atomicAdd(&red[ty * TM + 2 * i2],          sX);
            atomicAdd(&red[BM + ty * TM + 2 * i2],     s2X);
            atomicAdd(&red[ty * TM + 2 * i2 + 1],      sY);
            atomicAdd(&red[BM + ty * TM + 2 * i2 + 1], s2Y);
        }
        __syncthreads();
        if (tid < BM) {
            atomicAdd(&sBase[m0 + tid], red[tid]);
            atomicAdd(&sBase[CPc + m0 + tid], red[BM + tid]);
        }
    }
}

// ---------------------------------------------------------------------------
// BN finalize (all scales) + fused apply-sum over all 5 scales
// ---------------------------------------------------------------------------
__global__ void bn_finalize_k(const float* __restrict__ stat,
                              float* __restrict__ mean, float* __restrict__ istd)
{
    int s = blockIdx.x, c = threadIdx.x;
    const float inv = 1.0f / (float)(NB * NQc);
    float m = stat[s * 2 * CPc + c] * inv;
    float v = stat[s * 2 * CPc + CPc + c] * inv - m * m;
    mean[s * CPc + c] = m;
    istd[s * CPc + c] = rsqrtf(v + 1e-5f);
}

__global__ void bn_apply_all_k(const float* __restrict__ Z,
    const float* __restrict__ mean, const float* __restrict__ istd,
    const float* __restrict__ gm0, const float* __restrict__ bt0,
    const float* __restrict__ gm1, const float* __restrict__ bt1,
    const float* __restrict__ gm2, const float* __restrict__ bt2,
    const float* __restrict__ gm3, const float* __restrict__ bt3,
    const float* __restrict__ gm4, const float* __restrict__ bt4,
    float* __restrict__ out)
{
    const float* G[5]  = {gm0, gm1, gm2, gm3, gm4};
    const float* Bt[5] = {bt0, bt1, bt2, bt3, bt4};
    long i = ((long)blockIdx.x * 256 + threadIdx.x) * 4;
    int c = (int)((i / NQc) % CPc);
    float4 o = {0.f, 0.f, 0.f, 0.f};
#pragma unroll
    for (int s = 0; s < 5; s++) {
        float a = istd[s * CPc + c] * G[s][c];
        float bb = fmaf(-mean[s * CPc + c], a, Bt[s][c]);
        float4 z = *(const float4*)(Z + (long)s * ZSZ + i);
        o.x = fmaf(z.x, a, o.x + bb);
        o.y = fmaf(z.y, a, o.y + bb);
        o.z = fmaf(z.z, a, o.z + bb);
        o.w = fmaf(z.w, a, o.w + bb);
    }
    *(float4*)(out + i) = o;
}

// ---------------------------------------------------------------------------
// Host launch
// ---------------------------------------------------------------------------
extern "C" void kernel_launch(void* const* d_in, const int* in_sizes, int n_in,
                              void* d_out, int out_size)
{
    (void)in_sizes; (void)n_in; (void)out_size;

    const float* persp = (const float*)d_in[0];
    const float* resp[5] = {
        (const float*)d_in[1], (const float*)d_in[2], (const float*)d_in[3],
        (const float*)d_in[4], (const float*)d_in[5] };
    const float* t_w = (const float*)d_in[6];
    const float* z_w = (const float*)d_in[7];
    float* out = (float*)d_out;

    static const int MsH[5] = {2304, 2304, 576, 144, 36};
    static const long PGoffH[5] = {0L,
        (long)NB * 128 * 2304,
        (long)NB * 128 * (2304 + 2304),
        (long)NB * 128 * (2304 + 2304 + 576),
        (long)NB * 128 * (2304 + 2304 + 576 + 144)};

    float *T, *PG, *O, *Z, *stat, *mean, *istd;
    cudaGetSymbolAddress((void**)&T,    g_T);
    cudaGetSymbolAddress((void**)&PG,   g_PG);
    cudaGetSymbolAddress((void**)&O,    g_O);
    cudaGetSymbolAddress((void**)&Z,    g_Z);
    cudaGetSymbolAddress((void**)&stat, g_stat);
    cudaGetSymbolAddress((void**)&mean, g_mean);
    cudaGetSymbolAddress((void**)&istd, g_istd);

    const int FLASH_SMEM = 16896 * 4;
    cudaFuncSetAttribute(flash_k,
        cudaFuncAttributeMaxDynamicSharedMemorySize, FLASH_SMEM);

    // ---- zero split-K targets, then ONE projection launch ----
    cudaMemsetAsync(T,  0, (size_t)NB * PLc * NQc * 4, 0);
    cudaMemsetAsync(PG, 0, PG_TOTAL * 4, 0);

    ProjArgs pa;
    pa.W[0] = t_w;  pa.X[0] = persp;  pa.C[0] = T;
    for (int i = 0; i < 5; i++) {
        const float* p_w  = (const float*)d_in[8 + 4 * i];
        const float* g_wt = (const float*)d_in[9 + 4 * i];
        pa.W[1 + 2 * i] = p_w;   pa.X[1 + 2 * i] = resp[i];
        pa.C[1 + 2 * i] = PG + PGoffH[i];
        pa.W[2 + 2 * i] = g_wt;  pa.X[2 + 2 * i] = resp[i];
        pa.C[2 + 2 * i] = PG + PGoffH[i] + (long)PLc * MsH[i];
    }
    proj_k<<<1760, 256>>>(pa);

    // ---- merged flash attention over all 5 scales ----
    flash_k<<<dim3(NQc / 64, 5 * NB), 256, FLASH_SMEM>>>(T, PG, O);

    // ---- batched Z-GEMM (20 batches) with fused BN stats ----
    cudaMemsetAsync(stat, 0, (size_t)5 * 2 * CPc * 4, 0);
    {
        dim3 grid(NQc / 128, CPc / 64, 5 * NB);
        zgemm_k<64, 128, 4, 8><<<grid, 256>>>(
            z_w, O, Z, CPc, NQc, PLc, PLc, NQc, NQc,
            (long)NQc * PLc, (long)CPc * NQc, stat, NB);
    }

    bn_finalize_k<<<5, 256>>>(stat, mean, istd);

    {
        long total4 = (long)NB * CPc * NQc / 4;
        bn_apply_all_k<<<(unsigned)(total4 / 256), 256>>>(
            Z, mean, istd,
            (const float*)d_in[10], (const float*)d_in[11],
            (const float*)d_in[14], (const float*)d_in[15],
            (const float*)d_in[18], (const float*)d_in[19],
            (const float*)d_in[22], (const float*)d_in[23],
            (const float*)d_in[26], (const float*)d_in[27],
            out);
    }
}

// round 10
// speedup vs baseline: 1.5477x; 1.0405x over previous
#include <cuda_runtime.h>
#include <math.h>

#define NB   4
#define CPc  256
#define PLc  64
#define NQc  2304

typedef unsigned long long ull;

// per-scale M sizes and PG offsets (floats), compile-time
__constant__ int  d_Mi[5]    = {2304, 2304, 576, 144, 36};
__constant__ long d_PGoff[5] = {0L,
                                (long)NB * 128 * 2304,
                                (long)NB * 128 * (2304 + 2304),
                                (long)NB * 128 * (2304 + 2304 + 576),
                                (long)NB * 128 * (2304 + 2304 + 576 + 144)};
#define PG_TOTAL ((long)NB * 128 * (2304 + 2304 + 576 + 144 + 36))
#define OSZ ((long)NB * NQc * PLc)
#define CNTF ((float)(NB * NQc))

// ---------------------------------------------------------------------------
// Scratch
// ---------------------------------------------------------------------------
__device__ float g_T  [NB * PLc * NQc];
__device__ float g_PG [NB * 128 * (2304 + 2304 + 576 + 144 + 36)];
__device__ float g_O  [5 * NB * NQc * PLc];
__device__ float g_cov[5 * 4160];            // per scale: C[64][64] + mu[64]
__device__ float g_Wq [CPc * 320];           // stacked scaled weights
__device__ float g_cst[5 * CPc];             // per-scale affine constants

// ---------------------------------------------------------------------------
// Helpers
// ---------------------------------------------------------------------------
__device__ __forceinline__ float fexp(float x)
{
    x = fmaxf(x, -87.0f);
    const float L2E = 1.4426950408889634f;
    float t = fmaf(x, L2E, 12582912.0f);
    float n = t - 12582912.0f;
    float f = fmaf(x, L2E, -n);
    float p = 1.33335581e-3f;
    p = fmaf(p, f, 9.61812911e-3f);
    p = fmaf(p, f, 5.55041087e-2f);
    p = fmaf(p, f, 2.40226507e-1f);
    p = fmaf(p, f, 6.93147180e-1f);
    p = fmaf(p, f, 1.0f);
    int ni = (int)n;
    ni = max(-126, min(127, ni));
    return p * __int_as_float((ni + 127) << 23);
}

__device__ __forceinline__ void ffma2(ull& c, ull a, ull b)
{
    asm("fma.rn.f32x2 %0, %1, %2, %0;" : "+l"(c) : "l"(a), "l"(b));
}
__device__ __forceinline__ void fmul2(ull& c, ull b)
{
    asm("mul.rn.f32x2 %0, %0, %1;" : "+l"(c) : "l"(b));
}
__device__ __forceinline__ ull dup2(float x)
{
    ull r;
    unsigned u = __float_as_uint(x);
    asm("mov.b64 %0, {%1, %1};" : "=l"(r) : "r"(u));
    return r;
}
__device__ __forceinline__ ull pack2(float lo, float hi)
{
    ull r;
    asm("mov.b64 %0, {%1, %2};" : "=l"(r) : "f"(lo), "f"(hi));
    return r;
}

// ===========================================================================
// Unified projection launch: 11 segments (T, P0,G0, ... P4,G4).
// T segment is ks=1 now (no memset, no atomics).
// ===========================================================================
struct ProjArgs {
    const float* W[11];
    const float* X[11];
    float*       C[11];
};

__constant__ int  c_segN  [11] = {2304, 2304,2304, 2304,2304, 576,576, 144,144, 36,36};
__constant__ int  c_segK  [11] = {256, 64,64, 256,256, 512,512, 1024,1024, 2048,2048};
__constant__ int  c_segKs [11] = {1, 1,1, 2,2, 4,4, 8,8, 16,16};
__constant__ int  c_segKch[11] = {256, 64,64, 128,128, 128,128, 128,128, 128,128};
__constant__ int  c_segNt [11] = {36, 36,36, 36,36, 9,9, 3,3, 1,1};
__constant__ int  c_segStart[12] = {0,144,288,432,720,1008,1152,1296,1392,1488,1552,1616};
__constant__ long c_segSX [11] = {256L*2304, 64L*2304,64L*2304, 256L*2304,256L*2304,
                                  512L*576,512L*576, 1024L*144,1024L*144, 2048L*36,2048L*36};
__constant__ long c_segSC [11] = {64L*2304, 128L*2304,128L*2304, 128L*2304,128L*2304,
                                  128L*576,128L*576, 128L*144,128L*144, 128L*36,128L*36};

__global__ void __launch_bounds__(256) proj_k(ProjArgs pa)
{
    __shared__ float As[2][16][64];
    __shared__ float Bs[2][16][64];

    const int bid = blockIdx.x;
    int seg = 0;
#pragma unroll
    for (int s = 1; s < 11; s++) if (bid >= c_segStart[s]) seg = s;
    const int local = bid - c_segStart[seg];
    const int ntl = c_segNt[seg];
    const int nt = local % ntl;
    const int rest = local / ntl;
    const int ks = c_segKs[seg];
    const int kz = rest % ks;
    const int b  = rest / ks;

    const int N = c_segN[seg];
    const int K = c_segK[seg];
    const int kchunk = c_segKch[seg];
    const int kbeg = kz * kchunk;
    const int kend = min(K, kbeg + kchunk);
    const int n0 = nt * 64;

    const float* A  = pa.W[seg];
    const float* Bx = pa.X[seg] + (long)b * c_segSX[seg];
    float*       C  = pa.C[seg] + (long)b * c_segSC[seg];

    const int tid = threadIdx.x;
    const int ty = tid >> 4, tx = tid & 15;

    float4 ra, rb;
    const int am = tid >> 2, akq = (tid & 3) * 4;
    const int bk = tid >> 4, bnq = (tid & 15) * 4;
    const int bgn = n0 + bnq;

    auto fetchA = [&](int k0) {
        ra = *(const float4*)(A + (long)am * K + k0 + akq);
    };
    auto storeA = [&](int buf) {
        As[buf][akq + 0][am] = ra.x; As[buf][akq + 1][am] = ra.y;
        As[buf][akq + 2][am] = ra.z; As[buf][akq + 3][am] = ra.w;
    };
    auto fetchB = [&](int k0) {
        rb = make_float4(0.f, 0.f, 0.f, 0.f);
        if (bgn + 3 < N) rb = *(const float4*)(Bx + (long)(k0 + bk) * N + bgn);
    };
    auto storeB = [&](int buf) {
        *(float4*)&Bs[buf][bk][bnq] = rb;
    };

    ull acc2[2][4];
#pragma unroll
    for (int i = 0; i < 2; i++)
#pragma unroll
        for (int j = 0; j < 4; j++) acc2[i][j] = 0ULL;

    const int nkt = (kend - kbeg) / 16;

    fetchA(kbeg); fetchB(kbeg);
    storeA(0); storeB(0);
    __syncthreads();

    for (int t = 0; t < nkt; t++) {
        const int cur = t & 1, nxt = cur ^ 1;
        const bool more = (t + 1) < nkt;
        if (more) { fetchA(kbeg + (t + 1) * 16); fetchB(kbeg + (t + 1) * 16); }

#pragma unroll
        for (int kk = 0; kk < 16; kk++) {
            float4 a = *(const float4*)&As[cur][kk][ty * 4];
            const ull* a2 = (const ull*)&a;
            float4 bv = *(const float4*)&Bs[cur][kk][tx * 4];
            const float* bf = (const float*)&bv;
#pragma unroll
            for (int j = 0; j < 4; j++) {
                ull bd = dup2(bf[j]);
                ffma2(acc2[0][j], a2[0], bd);
                ffma2(acc2[1][j], a2[1], bd);
            }
        }

        if (more) { storeA(nxt); storeB(nxt); }
        __syncthreads();
    }

#pragma unroll
    for (int i2 = 0; i2 < 2; i2++) {
        int gmA = ty * 4 + 2 * i2;
#pragma unroll
        for (int j = 0; j < 4; j++) {
            int gn = n0 + tx * 4 + j;
            if (gn >= N) continue;
            float2 w = *(float2*)&acc2[i2][j];
            if (ks > 1) {
                atomicAdd(&C[(long)gmA * N + gn], w.x);
                atomicAdd(&C[(long)(gmA + 1) * N + gn], w.y);
            } else {
                C[(long)gmA * N + gn] = w.x;
                C[(long)(gmA + 1) * N + gn] = w.y;
            }
        }
    }
}

// ---------------------------------------------------------------------------
// Merged flash attention over ALL scales (unchanged from R8 — validated).
// ---------------------------------------------------------------------------
__global__ void __launch_bounds__(256) flash_k(
    const float* __restrict__ T, const float* __restrict__ PG,
    float* __restrict__ O)
{
    extern __shared__ float sm[];
    float (*Tq)[64] = (float(*)[64])(sm);
    float (*Ps)[64] = (float(*)[64])(sm + 4096);
    float (*Gs)[68] = (float(*)[68])(sm + 8192);
    float (*Pt)[68] = (float(*)[68])(sm + 12544);

    const int sc = blockIdx.y >> 2;
    const int b  = blockIdx.y & 3;
    const int Mi = d_Mi[sc];
    const int n0 = blockIdx.x * 64;
    const int tid = threadIdx.x;
    const int ty = tid >> 4, tx = tid & 15;

    const float* Tb = T + (long)b * PLc * NQc;
    const float* Pb = PG + d_PGoff[sc] + (long)b * 2 * PLc * Mi;
    const float* Gb = Pb + (long)PLc * Mi;
    float* Ob = O + (long)sc * OSZ + (long)b * NQc * PLc;

#pragma unroll
    for (int r = 0; r < 4; r++) {
        int e = (tid + r * 256) * 4;
        int k = e >> 6, q = e & 63;
        *(float4*)&Tq[k][q] = *(const float4*)(Tb + (long)k * NQc + n0 + q);
    }

    float Mrun[4], Srun[4];
#pragma unroll
    for (int q = 0; q < 4; q++) { Mrun[q] = -1e30f; Srun[q] = 0.f; }
    ull acco[2][4];
#pragma unroll
    for (int i = 0; i < 2; i++)
#pragma unroll
        for (int j = 0; j < 4; j++) acco[i][j] = 0ULL;

    for (int m0 = 0; m0 < Mi; m0 += 64) {
#pragma unroll
        for (int r = 0; r < 4; r++) {
            int e = (tid + r * 256) * 4;
            int k = e >> 6, mm = e & 63;
            float4 v = {0.f, 0.f, 0.f, 0.f};
            if (m0 + mm < Mi) v = *(const float4*)(Pb + (long)k * Mi + m0 + mm);
            *(float4*)&Ps[k][mm] = v;
        }
#pragma unroll
        for (int r = 0; r < 4; r++) {
            int e = tid + r * 256;
            int c = e >> 4, mq = (e & 15) * 4;
            float4 v = {0.f, 0.f, 0.f, 0.f};
            if (m0 + mq < Mi) v = *(const float4*)(Gb + (long)c * Mi + m0 + mq);
            Gs[mq + 0][c] = v.x; Gs[mq + 1][c] = v.y;
            Gs[mq + 2][c] = v.z; Gs[mq + 3][c] = v.w;
        }
        __syncthreads();

        ull accs[2][4];
#pragma unroll
        for (int i = 0; i < 2; i++)
#pragma unroll
            for (int j = 0; j < 4; j++) accs[i][j] = 0ULL;

#pragma unroll 16
        for (int kk = 0; kk < 64; kk++) {
            float4 a = *(const float4*)&Tq[kk][ty * 4];
            const ull* a2 = (const ull*)&a;
            float4 bv = *(const float4*)&Ps[kk][tx * 4];
            const float* bf = (const float*)&bv;
#pragma unroll
            for (int j = 0; j < 4; j++) {
                ull bd = dup2(bf[j]);
                ffma2(accs[0][j], a2[0], bd);
                ffma2(accs[1][j], a2[1], bd);
            }
        }

        float S[4][4];
#pragma unroll
        for (int qp = 0; qp < 2; qp++)
#pragma unroll
            for (int j = 0; j < 4; j++) {
                float2 w = *(float2*)&accs[qp][j];
                S[2 * qp][j] = w.x;
                S[2 * qp + 1][j] = w.y;
            }

        float tm[4];
#pragma unroll
        for (int q = 0; q < 4; q++)
            tm[q] = fmaxf(fmaxf(S[q][0], S[q][1]), fmaxf(S[q][2], S[q][3]));
#pragma unroll
        for (int s = 1; s < 16; s <<= 1) {
#pragma unroll
            for (int q = 0; q < 4; q++)
                tm[q] = fmaxf(tm[q], __shfl_xor_sync(0xFFFFFFFFu, tm[q], s));
        }

        float f[4], ls[4];
#pragma unroll
        for (int q = 0; q < 4; q++) {
            float Mn = fmaxf(Mrun[q], tm[q]);
            f[q] = fexp(Mrun[q] - Mn);
            Mrun[q] = Mn;
            ls[q] = 0.f;
        }

#pragma unroll
        for (int j = 0; j < 4; j++) {
            bool ok = (m0 + tx * 4 + j) < Mi;
#pragma unroll
            for (int q = 0; q < 4; q++) {
                float p = ok ? fexp(S[q][j] - Mrun[q]) : 0.f;
                S[q][j] = p;
                ls[q] += p;
            }
        }
#pragma unroll
        for (int s = 1; s < 16; s <<= 1) {
#pragma unroll
            for (int q = 0; q < 4; q++)
                ls[q] += __shfl_xor_sync(0xFFFFFFFFu, ls[q], s);
        }
#pragma unroll
        for (int q = 0; q < 4; q++)
            Srun[q] = fmaf(Srun[q], f[q], ls[q]);

        ull f01 = pack2(f[0], f[1]);
        ull f23 = pack2(f[2], f[3]);
#pragma unroll
        for (int j = 0; j < 4; j++) { fmul2(acco[0][j], f01); fmul2(acco[1][j], f23); }

#pragma unroll
        for (int j = 0; j < 4; j++) {
            float4 v = {S[0][j], S[1][j], S[2][j], S[3][j]};
            *(float4*)&Pt[tx * 4 + j][ty * 4] = v;
        }
        __syncthreads();

#pragma unroll 16
        for (int mm = 0; mm < 64; mm++) {
            float4 a = *(const float4*)&Pt[mm][ty * 4];
            const ull* a2 = (const ull*)&a;
            float4 bv = *(const float4*)&Gs[mm][tx * 4];
            const float* bf = (const float*)&bv;
#pragma unroll
            for (int j = 0; j < 4; j++) {
                ull bd = dup2(bf[j]);
                ffma2(acco[0][j], a2[0], bd);
                ffma2(acco[1][j], a2[1], bd);
            }
        }
        __syncthreads();
    }

    float inv[4];
#pragma unroll
    for (int q = 0; q < 4; q++) inv[q] = 1.0f / Srun[q];
#pragma unroll
    for (int q = 0; q < 4; q++) {
        float4 v;
        float* vv = (float*)&v;
#pragma unroll
        for (int j = 0; j < 4; j++) {
            float2 w = *(float2*)&acco[q >> 1][j];
            vv[j] = ((q & 1) ? w.y : w.x) * inv[q];
        }
        *(float4*)(Ob + ((long)n0 + ty * 4 + q) * PLc + tx * 4) = v;
    }
}

// ---------------------------------------------------------------------------
// Covariance of O_view columns per scale: C[k1][k2] = sum_{b,n} r_k1 r_k2,
// mu[k] = sum r_k.  O_view row k of (s,b) = O + s*OSZ + b*64*NQc + k*NQc.
// ---------------------------------------------------------------------------
__global__ void __launch_bounds__(256) cov_k(
    const float* __restrict__ O, float* __restrict__ cov)
{
    __shared__ float smv[32][68];
    const int s = blockIdx.y;
    const float* Os = O + (long)s * OSZ;
    float* Cs = cov + s * 4160;
    float* mus = Cs + 4096;

    const int tid = threadIdx.x;
    const int ty = tid >> 4, tx = tid & 15;

    ull acc2[2][4];
#pragma unroll
    for (int i = 0; i < 2; i++)
#pragma unroll
        for (int j = 0; j < 4; j++) acc2[i][j] = 0ULL;
    float mua[4] = {0.f, 0.f, 0.f, 0.f};

    for (int col0 = blockIdx.x * 32; col0 < NB * NQc; col0 += gridDim.x * 32) {
#pragma unroll
        for (int r = 0; r < 8; r++) {
            int e = tid + r * 256;
            int k = e >> 5, cc = e & 31;
            int col = col0 + cc;
            int b = col / NQc, n = col - b * NQc;
            smv[cc][k] = Os[((long)b * 64 + k) * NQc + n];
        }
        __syncthreads();

#pragma unroll
        for (int cc = 0; cc < 32; cc++) {
            float4 a = *(const float4*)&smv[cc][ty * 4];
            const ull* a2 = (const ull*)&a;
            float4 bv = *(const float4*)&smv[cc][tx * 4];
            const float* bf = (const float*)&bv;
#pragma unroll
            for (int j = 0; j < 4; j++) {
                ull bd = dup2(bf[j]);
                ffma2(acc2[0][j], a2[0], bd);
                ffma2(acc2[1][j], a2[1], bd);
            }
            if (tx == 0) { mua[0] += a.x; mua[1] += a.y; mua[2] += a.z; mua[3] += a.w; }
        }
        __syncthreads();
    }

#pragma unroll
    for (int i2 = 0; i2 < 2; i2++)
#pragma unroll
        for (int j = 0; j < 4; j++) {
            float2 w = *(float2*)&acc2[i2][j];
            atomicAdd(&Cs[(ty * 4 + 2 * i2) * 64 + tx * 4 + j], w.x);
            atomicAdd(&Cs[(ty * 4 + 2 * i2 + 1) * 64 + tx * 4 + j], w.y);
        }
    if (tx == 0) {
#pragma unroll
        for (int i = 0; i < 4; i++) atomicAdd(&mus[ty * 4 + i], mua[i]);
    }
}

// ---------------------------------------------------------------------------
// BN stats via quadratic form + build stacked scaled weights and constants.
// ---------------------------------------------------------------------------
struct StatsArgs { const float* gm[5]; const float* bt[5]; };

__global__ void __launch_bounds__(256) stats_k(
    const float* __restrict__ cov, const float* __restrict__ zw,
    StatsArgs sa, float* __restrict__ Wq, float* __restrict__ cst)
{
    __shared__ float Cs[64][64];
    __shared__ float mus[64];
    const int s = blockIdx.x;
    const float* Cg = cov + s * 4160;
    const int tid = threadIdx.x;

    for (int e = tid; e < 4096; e += 256) ((float*)Cs)[e] = Cg[e];
    if (tid < 64) mus[tid] = Cg[4096 + tid];
    __syncthreads();

    const int c = tid;
    float zr[64];
#pragma unroll
    for (int k = 0; k < 64; k += 4) {
        float4 v = *(const float4*)(zw + (long)c * 64 + k);
        zr[k] = v.x; zr[k + 1] = v.y; zr[k + 2] = v.z; zr[k + 3] = v.w;
    }
    ull zrp[32];
#pragma unroll
    for (int i = 0; i < 32; i++) zrp[i] = pack2(zr[2 * i], zr[2 * i + 1]);

    float m = 0.f;
#pragma unroll
    for (int k = 0; k < 64; k++) m = fmaf(zr[k], mus[k], m);
    const float inv = 1.0f / CNTF;
    m *= inv;

    float q = 0.f;
    for (int k1 = 0; k1 < 64; k1++) {
        ull t2 = 0ULL;
#pragma unroll
        for (int k2 = 0; k2 < 64; k2 += 2)
            ffma2(t2, *(const ull*)&Cs[k1][k2], zrp[k2 >> 1]);
        float2 tt = *(float2*)&t2;
        q = fmaf(zr[k1], tt.x + tt.y, q);
    }

    float var = q * inv - m * m;
    float a = sa.gm[s][c] * rsqrtf(var + 1e-5f);
    cst[s * CPc + c] = fmaf(-a, m, sa.bt[s][c]);
#pragma unroll
    for (int k = 0; k < 64; k++)
        Wq[(long)c * 320 + s * 64 + k] = a * zr[k];
}

// ---------------------------------------------------------------------------
// Final GEMM: out[b] = Wq[256,320] @ Ostack[320, 2304] + cvec.
// B rows r = s*64+k map to O + s*OSZ + b*64*NQc + k*NQc.
// ---------------------------------------------------------------------------
__global__ void __launch_bounds__(256) fin_k(
    const float* __restrict__ A, const float* __restrict__ O,
    const float* __restrict__ cst, float* __restrict__ out)
{
    __shared__ float As[2][16][64];
    __shared__ float Bs[2][16][128];

    const int b = blockIdx.z;
    const float* Bb = O + (long)b * (64 * NQc);
    float* Cc = out + (long)b * CPc * NQc;

    const int m0 = blockIdx.y * 64, n0 = blockIdx.x * 128;
    const int tid = threadIdx.x;
    const int ty = tid >> 4, tx = tid & 15;

    float4 ra, rb[2];
    const int am = tid >> 2, akq = (tid & 3) * 4;

    auto fetchA = [&](int k0) {
        ra = *(const float4*)(A + (long)(m0 + am) * 320 + k0 + akq);
    };
    auto storeA = [&](int buf) {
        As[buf][akq + 0][am] = ra.x; As[buf][akq + 1][am] = ra.y;
        As[buf][akq + 2][am] = ra.z; As[buf][akq + 3][am] = ra.w;
    };
    auto fetchB = [&](int k0) {
#pragma unroll
        for (int r = 0; r < 2; r++) {
            int e = tid + r * 256;
            int k = e >> 5, nq = (e & 31) * 4;
            int row = k0 + k;
            long off = (long)(row >> 6) * OSZ + (long)(row & 63) * NQc;
            rb[r] = *(const float4*)(Bb + off + n0 + nq);
        }
    };
    auto storeB = [&](int buf) {
#pragma unroll
        for (int r = 0; r < 2; r++) {
            int e = tid + r * 256;
            int k = e >> 5, nq = (e & 31) * 4;
            *(float4*)&Bs[buf][k][nq] = rb[r];
        }
    };

    ull acc2[2][8];
#pragma unroll
    for (int i = 0; i < 2; i++)
#pragma unroll
        for (int j = 0; j < 8; j++) acc2[i][j] = 0ULL;

    const int nkt = 320 / 16;

    fetchA(0); fetchB(0);
    storeA(0); storeB(0);
    __syncthreads();

    for (int t = 0; t < nkt; t++) {
        const int cur = t & 1, nxt = cur ^ 1;
        const bool more = (t + 1) < nkt;
        if (more) { fetchA((t + 1) * 16); fetchB((t + 1) * 16); }

#pragma unroll
        for (int kk = 0; kk < 16; kk++) {
            float4 a = *(const float4*)&As[cur][kk][ty * 4];
            const ull* a2 = (const ull*)&a;
            float4 bv0 = *(const float4*)&Bs[cur][kk][tx * 8];
            float4 bv1 = *(const float4*)&Bs[cur][kk][tx * 8 + 4];
            float bf[8] = {bv0.x, bv0.y, bv0.z, bv0.w, bv1.x, bv1.y, bv1.z, bv1.w};
#pragma unroll
            for (int j = 0; j < 8; j++) {
                ull bd = dup2(bf[j]);
                ffma2(acc2[0][j], a2[0], bd);
                ffma2(acc2[1][j], a2[1], bd);
            }
        }

        if (more) { storeA(nxt); storeB(nxt); }
        __syncthreads();
    }

#pragma unroll
    for (int i2 = 0; i2 < 2; i2++) {
        int gmA = m0 + ty * 4 + 2 * i2;
        int gmB = gmA + 1;
        float cvA = cst[gmA] + cst[CPc + gmA] + cst[2 * CPc + gmA]
                  + cst[3 * CPc + gmA] + cst[4 * CPc + gmA];
        float cvB = cst[gmB] + cst[CPc + gmB] + cst[2 * CPc + gmB]
                  + cst[3 * CPc + gmB] + cst[4 * CPc + gmB];
#pragma unroll
        for (int j = 0; j < 8; j++) {
            int gn = n0 + tx * 8 + j;
            float2 w = *(float2*)&acc2[i2][j];
            Cc[(long)gmA * NQc + gn] = w.x + cvA;
            Cc[(long)gmB * NQc + gn] = w.y + cvB;
        }
    }
}

// ---------------------------------------------------------------------------
// Host launch
// ---------------------------------------------------------------------------
extern "C" void kernel_launch(void* const* d_in, const int* in_sizes, int n_in,
                              void* d_out, int out_size)
{
    (void)in_sizes; (void)n_in; (void)out_size;

    const float* persp = (const float*)d_in[0];
    const float* resp[5] = {
        (const float*)d_in[1], (const float*)d_in[2], (const float*)d_in[3],
        (const float*)d_in[4], (const float*)d_in[5] };
    const float* t_w = (const float*)d_in[6];
    const float* z_w = (const float*)d_in[7];
    float* out = (float*)d_out;

    static const int MsH[5] = {2304, 2304, 576, 144, 36};
    static const long PGoffH[5] = {0L,
        (long)NB * 128 * 2304,
        (long)NB * 128 * (2304 + 2304),
        (long)NB * 128 * (2304 + 2304 + 576),
        (long)NB * 128 * (2304 + 2304 + 576 + 144)};

    float *T, *PG, *O, *cov, *Wq, *cst;
    cudaGetSymbolAddress((void**)&T,   g_T);
    cudaGetSymbolAddress((void**)&PG,  g_PG);
    cudaGetSymbolAddress((void**)&O,   g_O);
    cudaGetSymbolAddress((void**)&cov, g_cov);
    cudaGetSymbolAddress((void**)&Wq,  g_Wq);
    cudaGetSymbolAddress((void**)&cst, g_cst);

    const int FLASH_SMEM = 16896 * 4;
    cudaFuncSetAttribute(flash_k,
        cudaFuncAttributeMaxDynamicSharedMemorySize, FLASH_SMEM);

    // ---- projections (T direct-store; PG split-K needs zeroing) ----
    cudaMemsetAsync(PG, 0, PG_TOTAL * 4, 0);

    ProjArgs pa;
    pa.W[0] = t_w;  pa.X[0] = persp;  pa.C[0] = T;
    for (int i = 0; i < 5; i++) {
        const float* p_w  = (const float*)d_in[8 + 4 * i];
        const float* g_wt = (const float*)d_in[9 + 4 * i];
        pa.W[1 + 2 * i] = p_w;   pa.X[1 + 2 * i] = resp[i];
        pa.C[1 + 2 * i] = PG + PGoffH[i];
        pa.W[2 + 2 * i] = g_wt;  pa.X[2 + 2 * i] = resp[i];
        pa.C[2 + 2 * i] = PG + PGoffH[i] + (long)PLc * MsH[i];
    }
    proj_k<<<1616, 256>>>(pa);

    // ---- merged flash attention over all 5 scales ----
    flash_k<<<dim3(NQc / 64, 5 * NB), 256, FLASH_SMEM>>>(T, PG, O);

    // ---- covariance + stats (replaces Z materialization + BN passes) ----
    cudaMemsetAsync(cov, 0, (size_t)5 * 4160 * 4, 0);
    cov_k<<<dim3(48, 5), 256>>>(O, cov);

    StatsArgs sa;
    for (int i = 0; i < 5; i++) {
        sa.gm[i] = (const float*)d_in[10 + 4 * i];
        sa.bt[i] = (const float*)d_in[11 + 4 * i];
    }
    stats_k<<<5, 256>>>(cov, z_w, sa, Wq, cst);

    // ---- single stacked output GEMM: out = Wq @ Ostack + cvec ----
    fin_k<<<dim3(NQc / 128, CPc / 64, NB), 256>>>(Wq, O, cst, out);
}

// round 11
// speedup vs baseline: 1.6282x; 1.0520x over previous
#include <cuda_runtime.h>
#include <math.h>

#define NB   4
#define CPc  256
#define PLc  64
#define NQc  2304

typedef unsigned long long ull;

// per-scale M sizes and PG offsets (floats), compile-time
__constant__ int  d_Mi[5]    = {2304, 2304, 576, 144, 36};
__constant__ long d_PGoff[5] = {0L,
                                (long)NB * 128 * 2304,
                                (long)NB * 128 * (2304 + 2304),
                                (long)NB * 128 * (2304 + 2304 + 576),
                                (long)NB * 128 * (2304 + 2304 + 576 + 144)};
#define PG_TOTAL ((long)NB * 128 * (2304 + 2304 + 576 + 144 + 36))
#define OSZ ((long)NB * NQc * PLc)
#define CNTF ((float)(NB * NQc))

// ---------------------------------------------------------------------------
// Scratch
// ---------------------------------------------------------------------------
__device__ float g_T  [NB * PLc * NQc];
__device__ float g_PG [NB * 128 * (2304 + 2304 + 576 + 144 + 36)];
__device__ float g_O  [5 * NB * NQc * PLc];
__device__ float g_cov[5 * 4160];            // per scale: C[64][64] + mu[64]
__device__ float g_Wq [CPc * 320];           // stacked scaled weights
__device__ float g_cst[5 * CPc];             // per-scale affine constants

// ---------------------------------------------------------------------------
// Helpers
// ---------------------------------------------------------------------------
__device__ __forceinline__ float fexp(float x)
{
    // clamp both sides: keeps magic-number reduction valid AND prevents inf
    // if an extreme logit exceeds the statistical bound (never binds in-range).
    x = fmaxf(fminf(x, 80.0f), -87.0f);
    const float L2E = 1.4426950408889634f;
    float t = fmaf(x, L2E, 12582912.0f);
    float n = t - 12582912.0f;
    float f = fmaf(x, L2E, -n);
    float p = 1.33335581e-3f;
    p = fmaf(p, f, 9.61812911e-3f);
    p = fmaf(p, f, 5.55041087e-2f);
    p = fmaf(p, f, 2.40226507e-1f);
    p = fmaf(p, f, 6.93147180e-1f);
    p = fmaf(p, f, 1.0f);
    int ni = (int)n;
    ni = max(-126, min(127, ni));
    return p * __int_as_float((ni + 127) << 23);
}

__device__ __forceinline__ void ffma2(ull& c, ull a, ull b)
{
    asm("fma.rn.f32x2 %0, %1, %2, %0;" : "+l"(c) : "l"(a), "l"(b));
}
__device__ __forceinline__ ull dup2(float x)
{
    ull r;
    unsigned u = __float_as_uint(x);
    asm("mov.b64 %0, {%1, %1};" : "=l"(r) : "r"(u));
    return r;
}
__device__ __forceinline__ ull pack2(float lo, float hi)
{
    ull r;
    asm("mov.b64 %0, {%1, %2};" : "=l"(r) : "f"(lo), "f"(hi));
    return r;
}

// ===========================================================================
// Unified projection launch (validated R9).
// ===========================================================================
struct ProjArgs {
    const float* W[11];
    const float* X[11];
    float*       C[11];
};

__constant__ int  c_segN  [11] = {2304, 2304,2304, 2304,2304, 576,576, 144,144, 36,36};
__constant__ int  c_segK  [11] = {256, 64,64, 256,256, 512,512, 1024,1024, 2048,2048};
__constant__ int  c_segKs [11] = {1, 1,1, 2,2, 4,4, 8,8, 16,16};
__constant__ int  c_segKch[11] = {256, 64,64, 128,128, 128,128, 128,128, 128,128};
__constant__ int  c_segNt [11] = {36, 36,36, 36,36, 9,9, 3,3, 1,1};
__constant__ int  c_segStart[12] = {0,144,288,432,720,1008,1152,1296,1392,1488,1552,1616};
__constant__ long c_segSX [11] = {256L*2304, 64L*2304,64L*2304, 256L*2304,256L*2304,
                                  512L*576,512L*576, 1024L*144,1024L*144, 2048L*36,2048L*36};
__constant__ long c_segSC [11] = {64L*2304, 128L*2304,128L*2304, 128L*2304,128L*2304,
                                  128L*576,128L*576, 128L*144,128L*144, 128L*36,128L*36};

__global__ void __launch_bounds__(256) proj_k(ProjArgs pa)
{
    __shared__ float As[2][16][64];
    __shared__ float Bs[2][16][64];

    const int bid = blockIdx.x;
    int seg = 0;
#pragma unroll
    for (int s = 1; s < 11; s++) if (bid >= c_segStart[s]) seg = s;
    const int local = bid - c_segStart[seg];
    const int ntl = c_segNt[seg];
    const int nt = local % ntl;
    const int rest = local / ntl;
    const int ks = c_segKs[seg];
    const int kz = rest % ks;
    const int b  = rest / ks;

    const int N = c_segN[seg];
    const int K = c_segK[seg];
    const int kchunk = c_segKch[seg];
    const int kbeg = kz * kchunk;
    const int kend = min(K, kbeg + kchunk);
    const int n0 = nt * 64;

    const float* A  = pa.W[seg];
    const float* Bx = pa.X[seg] + (long)b * c_segSX[seg];
    float*       C  = pa.C[seg] + (long)b * c_segSC[seg];

    const int tid = threadIdx.x;
    const int ty = tid >> 4, tx = tid & 15;

    float4 ra, rb;
    const int am = tid >> 2, akq = (tid & 3) * 4;
    const int bk = tid >> 4, bnq = (tid & 15) * 4;
    const int bgn = n0 + bnq;

    auto fetchA = [&](int k0) {
        ra = *(const float4*)(A + (long)am * K + k0 + akq);
    };
    auto storeA = [&](int buf) {
        As[buf][akq + 0][am] = ra.x; As[buf][akq + 1][am] = ra.y;
        As[buf][akq + 2][am] = ra.z; As[buf][akq + 3][am] = ra.w;
    };
    auto fetchB = [&](int k0) {
        rb = make_float4(0.f, 0.f, 0.f, 0.f);
        if (bgn + 3 < N) rb = *(const float4*)(Bx + (long)(k0 + bk) * N + bgn);
    };
    auto storeB = [&](int buf) {
        *(float4*)&Bs[buf][bk][bnq] = rb;
    };

    ull acc2[2][4];
#pragma unroll
    for (int i = 0; i < 2; i++)
#pragma unroll
        for (int j = 0; j < 4; j++) acc2[i][j] = 0ULL;

    const int nkt = (kend - kbeg) / 16;

    fetchA(kbeg); fetchB(kbeg);
    storeA(0); storeB(0);
    __syncthreads();

    for (int t = 0; t < nkt; t++) {
        const int cur = t & 1, nxt = cur ^ 1;
        const bool more = (t + 1) < nkt;
        if (more) { fetchA(kbeg + (t + 1) * 16); fetchB(kbeg + (t + 1) * 16); }

#pragma unroll
        for (int kk = 0; kk < 16; kk++) {
            float4 a = *(const float4*)&As[cur][kk][ty * 4];
            const ull* a2 = (const ull*)&a;
            float4 bv = *(const float4*)&Bs[cur][kk][tx * 4];
            const float* bf = (const float*)&bv;
#pragma unroll
            for (int j = 0; j < 4; j++) {
                ull bd = dup2(bf[j]);
                ffma2(acc2[0][j], a2[0], bd);
                ffma2(acc2[1][j], a2[1], bd);
            }
        }

        if (more) { storeA(nxt); storeB(nxt); }
        __syncthreads();
    }

#pragma unroll
    for (int i2 = 0; i2 < 2; i2++) {
        int gmA = ty * 4 + 2 * i2;
#pragma unroll
        for (int j = 0; j < 4; j++) {
            int gn = n0 + tx * 4 + j;
            if (gn >= N) continue;
            float2 w = *(float2*)&acc2[i2][j];
            if (ks > 1) {
                atomicAdd(&C[(long)gmA * N + gn], w.x);
                atomicAdd(&C[(long)(gmA + 1) * N + gn], w.y);
            } else {
                C[(long)gmA * N + gn] = w.x;
                C[(long)(gmA + 1) * N + gn] = w.y;
            }
        }
    }
}

// ---------------------------------------------------------------------------
// Flash attention, direct-exp variant (no max tracking; args bounded ±~75).
// Per-thread partial exp-sums accumulate across tiles; ONE reduce at end.
// ---------------------------------------------------------------------------
__global__ void __launch_bounds__(256) flash_k(
    const float* __restrict__ T, const float* __restrict__ PG,
    float* __restrict__ O)
{
    extern __shared__ float sm[];
    float (*Tq)[64] = (float(*)[64])(sm);
    float (*Ps)[64] = (float(*)[64])(sm + 4096);
    float (*Gs)[68] = (float(*)[68])(sm + 8192);
    float (*Pt)[68] = (float(*)[68])(sm + 12544);

    const int sc = blockIdx.y >> 2;
    const int b  = blockIdx.y & 3;
    const int Mi = d_Mi[sc];
    const int n0 = blockIdx.x * 64;
    const int tid = threadIdx.x;
    const int ty = tid >> 4, tx = tid & 15;

    const float* Tb = T + (long)b * PLc * NQc;
    const float* Pb = PG + d_PGoff[sc] + (long)b * 2 * PLc * Mi;
    const float* Gb = Pb + (long)PLc * Mi;
    float* Ob = O + (long)sc * OSZ + (long)b * NQc * PLc;

#pragma unroll
    for (int r = 0; r < 4; r++) {
        int e = (tid + r * 256) * 4;
        int k = e >> 6, q = e & 63;
        *(float4*)&Tq[k][q] = *(const float4*)(Tb + (long)k * NQc + n0 + q);
    }

    float Srun[4] = {0.f, 0.f, 0.f, 0.f};   // per-thread partial exp sums
    ull acco[2][4];
#pragma unroll
    for (int i = 0; i < 2; i++)
#pragma unroll
        for (int j = 0; j < 4; j++) acco[i][j] = 0ULL;

    for (int m0 = 0; m0 < Mi; m0 += 64) {
#pragma unroll
        for (int r = 0; r < 4; r++) {
            int e = (tid + r * 256) * 4;
            int k = e >> 6, mm = e & 63;
            float4 v = {0.f, 0.f, 0.f, 0.f};
            if (m0 + mm < Mi) v = *(const float4*)(Pb + (long)k * Mi + m0 + mm);
            *(float4*)&Ps[k][mm] = v;
        }
#pragma unroll
        for (int r = 0; r < 4; r++) {
            int e = tid + r * 256;
            int c = e >> 4, mq = (e & 15) * 4;
            float4 v = {0.f, 0.f, 0.f, 0.f};
            if (m0 + mq < Mi) v = *(const float4*)(Gb + (long)c * Mi + m0 + mq);
            Gs[mq + 0][c] = v.x; Gs[mq + 1][c] = v.y;
            Gs[mq + 2][c] = v.z; Gs[mq + 3][c] = v.w;
        }
        __syncthreads();

        // ---- S GEMM ----
        ull accs[2][4];
#pragma unroll
        for (int i = 0; i < 2; i++)
#pragma unroll
            for (int j = 0; j < 4; j++) accs[i][j] = 0ULL;

#pragma unroll 16
        for (int kk = 0; kk < 64; kk++) {
            float4 a = *(const float4*)&Tq[kk][ty * 4];
            const ull* a2 = (const ull*)&a;
            float4 bv = *(const float4*)&Ps[kk][tx * 4];
            const float* bf = (const float*)&bv;
#pragma unroll
            for (int j = 0; j < 4; j++) {
                ull bd = dup2(bf[j]);
                ffma2(accs[0][j], a2[0], bd);
                ffma2(accs[1][j], a2[1], bd);
            }
        }

        // ---- direct exp + partial sums ----
        float S[4][4];
#pragma unroll
        for (int qp = 0; qp < 2; qp++)
#pragma unroll
            for (int j = 0; j < 4; j++) {
                float2 w = *(float2*)&accs[qp][j];
                S[2 * qp][j] = w.x;
                S[2 * qp + 1][j] = w.y;
            }

#pragma unroll
        for (int j = 0; j < 4; j++) {
            bool ok = (m0 + tx * 4 + j) < Mi;
#pragma unroll
            for (int q = 0; q < 4; q++) {
                float p = ok ? fexp(S[q][j]) : 0.f;
                S[q][j] = p;
                Srun[q] += p;
            }
        }

        // ---- write exp'd tile Pt[m][q] ----
#pragma unroll
        for (int j = 0; j < 4; j++) {
            float4 v = {S[0][j], S[1][j], S[2][j], S[3][j]};
            *(float4*)&Pt[tx * 4 + j][ty * 4] = v;
        }
        __syncthreads();

        // ---- O GEMM ----
#pragma unroll 16
        for (int mm = 0; mm < 64; mm++) {
            float4 a = *(const float4*)&Pt[mm][ty * 4];
            const ull* a2 = (const ull*)&a;
            float4 bv = *(const float4*)&Gs[mm][tx * 4];
            const float* bf = (const float*)&bv;
#pragma unroll
            for (int j = 0; j < 4; j++) {
                ull bd = dup2(bf[j]);
                ffma2(acco[0][j], a2[0], bd);
                ffma2(acco[1][j], a2[1], bd);
            }
        }
        __syncthreads();
    }

    // ---- one final sum-reduce over the 16 tx lanes ----
#pragma unroll
    for (int s = 1; s < 16; s <<= 1) {
#pragma unroll
        for (int q = 0; q < 4; q++)
            Srun[q] += __shfl_xor_sync(0xFFFFFFFFu, Srun[q], s);
    }

    float inv[4];
#pragma unroll
    for (int q = 0; q < 4; q++) inv[q] = 1.0f / Srun[q];
#pragma unroll
    for (int q = 0; q < 4; q++) {
        float4 v;
        float* vv = (float*)&v;
#pragma unroll
        for (int j = 0; j < 4; j++) {
            float2 w = *(float2*)&acco[q >> 1][j];
            vv[j] = ((q & 1) ? w.y : w.x) * inv[q];
        }
        *(float4*)(Ob + ((long)n0 + ty * 4 + q) * PLc + tx * 4) = v;
    }
}

// ---------------------------------------------------------------------------
// Covariance of O_view columns per scale (validated R9).
// ---------------------------------------------------------------------------
__global__ void __launch_bounds__(256) cov_k(
    const float* __restrict__ O, float* __restrict__ cov)
{
    __shared__ float smv[32][68];
    const int s = blockIdx.y;
    const float* Os = O + (long)s * OSZ;
    float* Cs = cov + s * 4160;
    float* mus = Cs + 4096;

    const int tid = threadIdx.x;
    const int ty = tid >> 4, tx = tid & 15;

    ull acc2[2][4];
#pragma unroll
    for (int i = 0; i < 2; i++)
#pragma unroll
        for (int j = 0; j < 4; j++) acc2[i][j] = 0ULL;
    float mua[4] = {0.f, 0.f, 0.f, 0.f};

    for (int col0 = blockIdx.x * 32; col0 < NB * NQc; col0 += gridDim.x * 32) {
#pragma unroll
        for (int r = 0; r < 8; r++) {
            int e = tid + r * 256;
            int k = e >> 5, cc = e & 31;
            int col = col0 + cc;
            int b = col / NQc, n = col - b * NQc;
            smv[cc][k] = Os[((long)b * 64 + k) * NQc + n];
        }
        __syncthreads();

#pragma unroll
        for (int cc = 0; cc < 32; cc++) {
            float4 a = *(const float4*)&smv[cc][ty * 4];
            const ull* a2 = (const ull*)&a;
            float4 bv = *(const float4*)&smv[cc][tx * 4];
            const float* bf = (const float*)&bv;
#pragma unroll
            for (int j = 0; j < 4; j++) {
                ull bd = dup2(bf[j]);
                ffma2(acc2[0][j], a2[0], bd);
                ffma2(acc2[1][j], a2[1], bd);
            }
            if (tx == 0) { mua[0] += a.x; mua[1] += a.y; mua[2] += a.z; mua[3] += a.w; }
        }
        __syncthreads();
    }

#pragma unroll
    for (int i2 = 0; i2 < 2; i2++)
#pragma unroll
        for (int j = 0; j < 4; j++) {
            float2 w = *(float2*)&acc2[i2][j];
            atomicAdd(&Cs[(ty * 4 + 2 * i2) * 64 + tx * 4 + j], w.x);
            atomicAdd(&Cs[(ty * 4 + 2 * i2 + 1) * 64 + tx * 4 + j], w.y);
        }
    if (tx == 0) {
#pragma unroll
        for (int i = 0; i < 4; i++) atomicAdd(&mus[ty * 4 + i], mua[i]);
    }
}

// ---------------------------------------------------------------------------
// BN stats via quadratic form — parallelized: grid (5, 8); 8 threads/channel
// split the 64 k1 rows; shfl-butterfly reduce within the 8-lane groups.
// ---------------------------------------------------------------------------
struct StatsArgs { const float* gm[5]; const float* bt[5]; };

__global__ void __launch_bounds__(256) stats_k(
    const float* __restrict__ cov, const float* __restrict__ zw,
    StatsArgs sa, float* __restrict__ Wq, float* __restrict__ cst)
{
    __shared__ float Cs[64][64];
    __shared__ float mus[64];
    const int s = blockIdx.x;
    const float* Cg = cov + s * 4160;
    const int tid = threadIdx.x;

    for (int e = tid; e < 4096; e += 256) ((float*)Cs)[e] = Cg[e];
    if (tid < 64) mus[tid] = Cg[4096 + tid];
    __syncthreads();

    const int ch   = tid >> 3;                    // 0..31
    const int part = tid & 7;                     // 0..7
    const int c    = blockIdx.y * 32 + ch;
    const int k1b  = part * 8;

    float zr[64];
#pragma unroll
    for (int k = 0; k < 64; k += 4) {
        float4 v = *(const float4*)(zw + (long)c * 64 + k);
        zr[k] = v.x; zr[k + 1] = v.y; zr[k + 2] = v.z; zr[k + 3] = v.w;
    }
    ull zrp[32];
#pragma unroll
    for (int i = 0; i < 32; i++) zrp[i] = pack2(zr[2 * i], zr[2 * i + 1]);

    // partial mean and quadratic form over k1 in [k1b, k1b+8)
    float m = 0.f, q = 0.f;
#pragma unroll
    for (int r = 0; r < 8; r++) {
        int k1 = k1b + r;
        m = fmaf(zr[k1], mus[k1], m);
        ull t2 = 0ULL;
#pragma unroll
        for (int k2 = 0; k2 < 64; k2 += 2)
            ffma2(t2, *(const ull*)&Cs[k1][k2], zrp[k2 >> 1]);
        float2 tt = *(float2*)&t2;
        q = fmaf(zr[k1], tt.x + tt.y, q);
    }

    // reduce over the 8-lane group (xor 1,2,4 stays within group)
#pragma unroll
    for (int st = 1; st < 8; st <<= 1) {
        m += __shfl_xor_sync(0xFFFFFFFFu, m, st);
        q += __shfl_xor_sync(0xFFFFFFFFu, q, st);
    }

    const float inv = 1.0f / CNTF;
    m *= inv;
    float var = q * inv - m * m;
    float a = sa.gm[s][c] * rsqrtf(var + 1e-5f);
    if (part == 0)
        cst[s * CPc + c] = fmaf(-a, m, sa.bt[s][c]);
#pragma unroll
    for (int r = 0; r < 8; r++) {
        int k = k1b + r;
        Wq[(long)c * 320 + s * 64 + k] = a * zr[k];
    }
}

// ---------------------------------------------------------------------------
// Final GEMM: out[b] = Wq[256,320] @ Ostack[320, 2304] + cvec (validated R9).
// ---------------------------------------------------------------------------
__global__ void __launch_bounds__(256) fin_k(
    const float* __restrict__ A, const float* __restrict__ O,
    const float* __restrict__ cst, float* __restrict__ out)
{
    __shared__ float As[2][16][64];
    __shared__ float Bs[2][16][128];

    const int b = blockIdx.z;
    const float* Bb = O + (long)b * (64 * NQc);
    float* Cc = out + (long)b * CPc * NQc;

    const int m0 = blockIdx.y * 64, n0 = blockIdx.x * 128;
    const int tid = threadIdx.x;
    const int ty = tid >> 4, tx = tid & 15;

    float4 ra, rb[2];
    const int am = tid >> 2, akq = (tid & 3) * 4;

    auto fetchA = [&](int k0) {
        ra = *(const float4*)(A + (long)(m0 + am) * 320 + k0 + akq);
    };
    auto storeA = [&](int buf) {
        As[buf][akq + 0][am] = ra.x; As[buf][akq + 1][am] = ra.y;
        As[buf][akq + 2][am] = ra.z; As[buf][akq + 3][am] = ra.w;
    };
    auto fetchB = [&](int k0) {
#pragma unroll
        for (int r = 0; r < 2; r++) {
            int e = tid + r * 256;
            int k = e >> 5, nq = (e & 31) * 4;
            int row = k0 + k;
            long off = (long)(row >> 6) * OSZ + (long)(row & 63) * NQc;
            rb[r] = *(const float4*)(Bb + off + n0 + nq);
        }
    };
    auto storeB = [&](int buf) {
#pragma unroll
        for (int r = 0; r < 2; r++) {
            int e = tid + r * 256;
            int k = e >> 5, nq = (e & 31) * 4;
            *(float4*)&Bs[buf][k][nq] = rb[r];
        }
    };

    ull acc2[2][8];
#pragma unroll
    for (int i = 0; i < 2; i++)
#pragma unroll
        for (int j = 0; j < 8; j++) acc2[i][j] = 0ULL;

    const int nkt = 320 / 16;

    fetchA(0); fetchB(0);
    storeA(0); storeB(0);
    __syncthreads();

    for (int t = 0; t < nkt; t++) {
        const int cur = t & 1, nxt = cur ^ 1;
        const bool more = (t + 1) < nkt;
        if (more) { fetchA((t + 1) * 16); fetchB((t + 1) * 16); }

#pragma unroll
        for (int kk = 0; kk < 16; kk++) {
            float4 a = *(const float4*)&As[cur][kk][ty * 4];
            const ull* a2 = (const ull*)&a;
            float4 bv0 = *(const float4*)&Bs[cur][kk][tx * 8];
            float4 bv1 = *(const float4*)&Bs[cur][kk][tx * 8 + 4];
            float bf[8] = {bv0.x, bv0.y, bv0.z, bv0.w, bv1.x, bv1.y, bv1.z, bv1.w};
#pragma unroll
            for (int j = 0; j < 8; j++) {
                ull bd = dup2(bf[j]);
                ffma2(acc2[0][j], a2[0], bd);
                ffma2(acc2[1][j], a2[1], bd);
            }
        }

        if (more) { storeA(nxt); storeB(nxt); }
        __syncthreads();
    }

#pragma unroll
    for (int i2 = 0; i2 < 2; i2++) {
        int gmA = m0 + ty * 4 + 2 * i2;
        int gmB = gmA + 1;
        float cvA = cst[gmA] + cst[CPc + gmA] + cst[2 * CPc + gmA]
                  + cst[3 * CPc + gmA] + cst[4 * CPc + gmA];
        float cvB = cst[gmB] + cst[CPc + gmB] + cst[2 * CPc + gmB]
                  + cst[3 * CPc + gmB] + cst[4 * CPc + gmB];
#pragma unroll
        for (int j = 0; j < 8; j++) {
            int gn = n0 + tx * 8 + j;
            float2 w = *(float2*)&acc2[i2][j];
            Cc[(long)gmA * NQc + gn] = w.x + cvA;
            Cc[(long)gmB * NQc + gn] = w.y + cvB;
        }
    }
}

// ---------------------------------------------------------------------------
// Host launch
// ---------------------------------------------------------------------------
extern "C" void kernel_launch(void* const* d_in, const int* in_sizes, int n_in,
                              void* d_out, int out_size)
{
    (void)in_sizes; (void)n_in; (void)out_size;

    const float* persp = (const float*)d_in[0];
    const float* resp[5] = {
        (const float*)d_in[1], (const float*)d_in[2], (const float*)d_in[3],
        (const float*)d_in[4], (const float*)d_in[5] };
    const float* t_w = (const float*)d_in[6];
    const float* z_w = (const float*)d_in[7];
    float* out = (float*)d_out;

    static const int MsH[5] = {2304, 2304, 576, 144, 36};
    static const long PGoffH[5] = {0L,
        (long)NB * 128 * 2304,
        (long)NB * 128 * (2304 + 2304),
        (long)NB * 128 * (2304 + 2304 + 576),
        (long)NB * 128 * (2304 + 2304 + 576 + 144)};

    float *T, *PG, *O, *cov, *Wq, *cst;
    cudaGetSymbolAddress((void**)&T,   g_T);
    cudaGetSymbolAddress((void**)&PG,  g_PG);
    cudaGetSymbolAddress((void**)&O,   g_O);
    cudaGetSymbolAddress((void**)&cov, g_cov);
    cudaGetSymbolAddress((void**)&Wq,  g_Wq);
    cudaGetSymbolAddress((void**)&cst, g_cst);

    const int FLASH_SMEM = 16896 * 4;
    cudaFuncSetAttribute(flash_k,
        cudaFuncAttributeMaxDynamicSharedMemorySize, FLASH_SMEM);

    // ---- projections ----
    cudaMemsetAsync(PG, 0, PG_TOTAL * 4, 0);

    ProjArgs pa;
    pa.W[0] = t_w;  pa.X[0] = persp;  pa.C[0] = T;
    for (int i = 0; i < 5; i++) {
        const float* p_w  = (const float*)d_in[8 + 4 * i];
        const float* g_wt = (const float*)d_in[9 + 4 * i];
        pa.W[1 + 2 * i] = p_w;   pa.X[1 + 2 * i] = resp[i];
        pa.C[1 + 2 * i] = PG + PGoffH[i];
        pa.W[2 + 2 * i] = g_wt;  pa.X[2 + 2 * i] = resp[i];
        pa.C[2 + 2 * i] = PG + PGoffH[i] + (long)PLc * MsH[i];
    }
    proj_k<<<1616, 256>>>(pa);

    // ---- merged flash attention over all 5 scales ----
    flash_k<<<dim3(NQc / 64, 5 * NB), 256, FLASH_SMEM>>>(T, PG, O);

    // ---- covariance + stats ----
    cudaMemsetAsync(cov, 0, (size_t)5 * 4160 * 4, 0);
    cov_k<<<dim3(48, 5), 256>>>(O, cov);

    StatsArgs sa;
    for (int i = 0; i < 5; i++) {
        sa.gm[i] = (const float*)d_in[10 + 4 * i];
        sa.bt[i] = (const float*)d_in[11 + 4 * i];
    }
    stats_k<<<dim3(5, 8), 256>>>(cov, z_w, sa, Wq, cst);

    // ---- single stacked output GEMM ----
    fin_k<<<dim3(NQc / 128, CPc / 64, NB), 256>>>(Wq, O, cst, out);
}